// round 1
// baseline (speedup 1.0000x reference)
#include <cuda_runtime.h>
#include <math.h>

// Scratch (allocation-free rule: __device__ globals)
__device__ float g_norm[8192 * 1024];
__device__ float g_G[1024 * 1024];
__device__ float g_M[1024 * 1024];

// ---------------- row L2 normalize ----------------
// one block per row, 256 threads, d = 1024 (256 float4)
__global__ void k_normalize(const float* __restrict__ x, float* __restrict__ nrm, int d) {
    int row = blockIdx.x;
    const float4* xr = (const float4*)(x + (size_t)row * d);
    float4* nr = (float4*)(nrm + (size_t)row * d);

    float4 v = xr[threadIdx.x];
    float s = v.x * v.x + v.y * v.y + v.z * v.z + v.w * v.w;

    // warp reduce
    #pragma unroll
    for (int off = 16; off > 0; off >>= 1)
        s += __shfl_xor_sync(0xffffffffu, s, off);

    __shared__ float red[8];
    int lane = threadIdx.x & 31, wid = threadIdx.x >> 5;
    if (lane == 0) red[wid] = s;
    __syncthreads();
    if (wid == 0) {
        float t = (lane < 8) ? red[lane] : 0.0f;
        #pragma unroll
        for (int off = 4; off > 0; off >>= 1)
            t += __shfl_xor_sync(0xffffffffu, t, off);
        if (lane == 0) red[0] = t;
    }
    __syncthreads();
    float inv = 1.0f / fmaxf(sqrtf(red[0]), 1e-12f);
    v.x *= inv; v.y *= inv; v.z *= inv; v.w *= inv;
    nr[threadIdx.x] = v;
}

// ---------------- GEMM TN: C[M,N] = A^T * B, A:[K,M], B:[K,N] ----------------
// 64x64 tile, BK=16, 256 threads, 4x4 microtile
#define TBM 64
#define TBN 64
#define TBK 16
__global__ __launch_bounds__(256) void k_gemm_tn(
    const float* __restrict__ A, const float* __restrict__ B, float* __restrict__ C,
    int M, int N, int K)
{
    __shared__ float As[TBK][TBM];
    __shared__ float Bs[TBK][TBN];

    int t = threadIdx.x;
    int tx = t & 15, ty = t >> 4;
    int i0 = blockIdx.y * TBM;
    int j0 = blockIdx.x * TBN;

    float acc[4][4] = {};

    for (int k0 = 0; k0 < K; k0 += TBK) {
        #pragma unroll
        for (int s = 0; s < 4; s++) {
            int e = t + s * 256;
            int r = e >> 6, c = e & 63;
            As[r][c] = A[(size_t)(k0 + r) * M + i0 + c];
            Bs[r][c] = B[(size_t)(k0 + r) * N + j0 + c];
        }
        __syncthreads();

        #pragma unroll
        for (int kk = 0; kk < TBK; kk++) {
            float4 a = *(const float4*)&As[kk][ty * 4];
            float4 b = *(const float4*)&Bs[kk][tx * 4];
            float av[4] = {a.x, a.y, a.z, a.w};
            float bv[4] = {b.x, b.y, b.z, b.w};
            #pragma unroll
            for (int i = 0; i < 4; i++)
                #pragma unroll
                for (int j = 0; j < 4; j++)
                    acc[i][j] += av[i] * bv[j];
        }
        __syncthreads();
    }

    #pragma unroll
    for (int i = 0; i < 4; i++) {
        float4 o = make_float4(acc[i][0], acc[i][1], acc[i][2], acc[i][3]);
        *(float4*)&C[(size_t)(i0 + ty * 4 + i) * N + j0 + tx * 4] = o;
    }
}

// ---------------- GEMM NN: C[M,N] = A * B, A:[M,K], B:[K,N] ----------------
// 128x128 tile, BK=8, 256 threads, 8x8 microtile
#define BM 128
#define BN 128
#define BK 8
__global__ __launch_bounds__(256) void k_gemm_nn(
    const float* __restrict__ A, const float* __restrict__ B, float* __restrict__ C,
    int M, int N, int K)
{
    __shared__ float As[BK][BM];
    __shared__ float Bs[BK][BN];

    int t = threadIdx.x;
    int tx = t & 15, ty = t >> 4;
    int i0 = blockIdx.y * BM;
    int j0 = blockIdx.x * BN;

    int arow = t >> 1, acol = (t & 1) * 4;      // 128 rows x 8 cols, float4
    int brow = t >> 5, bcol = (t & 31) * 4;     // 8 rows x 128 cols, float4

    float acc[8][8] = {};

    for (int k0 = 0; k0 < K; k0 += BK) {
        float4 av = *(const float4*)&A[(size_t)(i0 + arow) * K + k0 + acol];
        As[acol + 0][arow] = av.x;
        As[acol + 1][arow] = av.y;
        As[acol + 2][arow] = av.z;
        As[acol + 3][arow] = av.w;
        *(float4*)&Bs[brow][bcol] = *(const float4*)&B[(size_t)(k0 + brow) * N + j0 + bcol];
        __syncthreads();

        #pragma unroll
        for (int kk = 0; kk < BK; kk++) {
            float a[8], b[8];
            *(float4*)&a[0] = *(float4*)&As[kk][ty * 8];
            *(float4*)&a[4] = *(float4*)&As[kk][ty * 8 + 4];
            *(float4*)&b[0] = *(float4*)&Bs[kk][tx * 8];
            *(float4*)&b[4] = *(float4*)&Bs[kk][tx * 8 + 4];
            #pragma unroll
            for (int i = 0; i < 8; i++)
                #pragma unroll
                for (int j = 0; j < 8; j++)
                    acc[i][j] += a[i] * b[j];
        }
        __syncthreads();
    }

    #pragma unroll
    for (int i = 0; i < 8; i++) {
        int r = i0 + ty * 8 + i;
        *(float4*)&C[(size_t)r * N + j0 + tx * 8]     = make_float4(acc[i][0], acc[i][1], acc[i][2], acc[i][3]);
        *(float4*)&C[(size_t)r * N + j0 + tx * 8 + 4] = make_float4(acc[i][4], acc[i][5], acc[i][6], acc[i][7]);
    }
}

extern "C" void kernel_launch(void* const* d_in, const int* in_sizes, int n_in,
                              void* d_out, int out_size)
{
    const float* x = (const float*)d_in[0];       // [n, d]
    const float* w = (const float*)d_in[1];       // [d, d]
    float* out = (float*)d_out;                   // [n, d]

    // derive shapes: weight is d x d
    int d = (int)(sqrt((double)in_sizes[1]) + 0.5);
    int n = in_sizes[0] / d;

    float *nrm, *G, *Mb;
    cudaGetSymbolAddress((void**)&nrm, g_norm);
    cudaGetSymbolAddress((void**)&G, g_G);
    cudaGetSymbolAddress((void**)&Mb, g_M);

    // 1) norm = row_l2_normalize(x)
    k_normalize<<<n, 256>>>(x, nrm, d);

    // 2) G = norm^T @ x   [d, d], K = n
    {
        dim3 grid(d / TBN, d / TBM);
        k_gemm_tn<<<grid, 256>>>(nrm, x, G, d, d, n);
    }

    // 3) M = G @ W   [d, d]
    {
        dim3 grid(d / BN, d / BM);
        k_gemm_nn<<<grid, 256>>>(G, w, Mb, d, d, d);
    }

    // 4) out = norm @ M   [n, d]
    {
        dim3 grid(d / BN, n / BM);
        k_gemm_nn<<<grid, 256>>>(nrm, Mb, out, n, d, d);
    }
}

// round 5
// speedup vs baseline: 1.7464x; 1.7464x over previous
#include <cuda_runtime.h>
#include <cuda_fp16.h>
#include <math.h>
#include <stdint.h>

#define NROWS 8192
#define DDIM  1024
#define ZSPLIT 8

// ---------------- scratch (device globals; no allocation) ----------------
__device__ float  g_norm  [NROWS * DDIM];
__device__ __half g_norm_h[NROWS * DDIM];
__device__ __half g_norm_l[NROWS * DDIM];
__device__ __half g_normT_h[DDIM * NROWS];
__device__ __half g_normT_l[DDIM * NROWS];
__device__ __half g_xT_h  [DDIM * NROWS];
__device__ __half g_xT_l  [DDIM * NROWS];
__device__ __half g_WT_h  [DDIM * DDIM];
__device__ __half g_WT_l  [DDIM * DDIM];
__device__ float  g_Gpart [ZSPLIT * DDIM * DDIM];
__device__ __half g_G_h   [DDIM * DDIM];
__device__ __half g_G_l   [DDIM * DDIM];
__device__ float  g_M     [DDIM * DDIM];
__device__ __half g_MT_h  [DDIM * DDIM];
__device__ __half g_MT_l  [DDIM * DDIM];

// ---------------- PTX helpers (plain sm_103-legal subset) ----------------
__device__ __forceinline__ uint32_t smem_u32(const void* p) {
    uint32_t a;
    asm("{ .reg .u64 t; cvta.to.shared.u64 t, %1; cvt.u32.u64 %0, t; }" : "=r"(a) : "l"(p));
    return a;
}
__device__ __forceinline__ void cp16(uint32_t dst, const void* src) {
    asm volatile("cp.async.cg.shared.global [%0], [%1], 16;" :: "r"(dst), "l"(src));
}
#define CP_COMMIT() asm volatile("cp.async.commit_group;" ::: "memory")
#define CP_WAIT1()  asm volatile("cp.async.wait_group 1;" ::: "memory")

__device__ __forceinline__ void ldsm4(uint32_t* r, uint32_t addr) {
    asm volatile("ldmatrix.sync.aligned.m8n8.x4.shared.b16 {%0,%1,%2,%3}, [%4];"
                 : "=r"(r[0]), "=r"(r[1]), "=r"(r[2]), "=r"(r[3]) : "r"(addr));
}
__device__ __forceinline__ void mma16816(float* c, const uint32_t* a, const uint32_t* b) {
    asm volatile(
        "mma.sync.aligned.m16n8k16.row.col.f32.f16.f16.f32 "
        "{%0,%1,%2,%3}, {%4,%5,%6,%7}, {%8,%9}, {%0,%1,%2,%3};"
        : "+f"(c[0]), "+f"(c[1]), "+f"(c[2]), "+f"(c[3])
        : "r"(a[0]), "r"(a[1]), "r"(a[2]), "r"(a[3]), "r"(b[0]), "r"(b[1]));
}

// ---------------- row L2 normalize + fp16 hi/lo split ----------------
__global__ void k_normalize(const float* __restrict__ x, float* __restrict__ nrm,
                            __half* __restrict__ nh, __half* __restrict__ nl) {
    int row = blockIdx.x;
    const float4* xr = (const float4*)(x + (size_t)row * DDIM);
    float4 v = xr[threadIdx.x];
    float s = v.x * v.x + v.y * v.y + v.z * v.z + v.w * v.w;
    #pragma unroll
    for (int o = 16; o > 0; o >>= 1) s += __shfl_xor_sync(0xffffffffu, s, o);
    __shared__ float red[8];
    int lane = threadIdx.x & 31, wid = threadIdx.x >> 5;
    if (lane == 0) red[wid] = s;
    __syncthreads();
    if (wid == 0) {
        float t = (lane < 8) ? red[lane] : 0.0f;
        #pragma unroll
        for (int o = 4; o > 0; o >>= 1) t += __shfl_xor_sync(0xffffffffu, t, o);
        if (lane == 0) red[0] = t;
    }
    __syncthreads();
    float inv = 1.0f / fmaxf(sqrtf(red[0]), 1e-12f);
    v.x *= inv; v.y *= inv; v.z *= inv; v.w *= inv;
    ((float4*)(nrm + (size_t)row * DDIM))[threadIdx.x] = v;
    size_t base = (size_t)row * DDIM + threadIdx.x * 4;
    float vv[4] = {v.x, v.y, v.z, v.w};
    #pragma unroll
    for (int j = 0; j < 4; j++) {
        __half h = __float2half_rn(vv[j]);
        nh[base + j] = h;
        nl[base + j] = __float2half_rn(vv[j] - __half2float(h));
    }
}

// ---------------- transpose + split: src[R,C] fp32 -> dst[C,R] fp16 hi/lo ----------------
__global__ void k_tsplit(const float* __restrict__ src,
                         __half* __restrict__ dh, __half* __restrict__ dl,
                         int R, int C) {
    __shared__ float tile[32][33];
    int c0 = blockIdx.x * 32, r0 = blockIdx.y * 32;
    #pragma unroll
    for (int i = threadIdx.y; i < 32; i += 8)
        tile[i][threadIdx.x] = src[(size_t)(r0 + i) * C + c0 + threadIdx.x];
    __syncthreads();
    #pragma unroll
    for (int i = threadIdx.y; i < 32; i += 8) {
        float v = tile[threadIdx.x][i];
        __half h = __float2half_rn(v);
        size_t o = (size_t)(c0 + i) * R + r0 + threadIdx.x;
        dh[o] = h;
        dl[o] = __float2half_rn(v - __half2float(h));
    }
}

// ---------------- reduce ZSPLIT partials + split ----------------
__global__ void k_reduce_split(const float* __restrict__ p,
                               __half* __restrict__ dh, __half* __restrict__ dl) {
    int i = blockIdx.x * blockDim.x + threadIdx.x;
    const int n = DDIM * DDIM;
    float s = 0.0f;
    #pragma unroll
    for (int z = 0; z < ZSPLIT; z++) s += p[i + z * n];
    __half h = __float2half_rn(s);
    dh[i] = h;
    dl[i] = __float2half_rn(s - __half2float(h));
}

// ---------------- fp16x3 HMMA GEMM: C[i0+..,j0+..] = sum_k A[i,k]*B[j,k] ----------------
// Block tile 128x128, BK=32 halfs. SMEM row = 128B: [hi 4x16B | lo 4x16B], chunk-swizzled.
// stage layout: A tile 16KB @ 0, B tile 16KB @ 16384. Two stages.
#define STAGE_BYTES 32768

__global__ __launch_bounds__(256) void k_mma_gemm(
    const __half* __restrict__ Ah, const __half* __restrict__ Al,
    const __half* __restrict__ Bh, const __half* __restrict__ Bl,
    float* __restrict__ C, int ldk, int kPerZ, int ldc, int partStride)
{
    extern __shared__ char smem[];
    uint32_t sbase = smem_u32(smem);
    int t = threadIdx.x;
    int lane = t & 31, w = t >> 5;
    int wm = w >> 2, wn = w & 3;                 // warp grid 2 x 4
    int i0 = blockIdx.y * 128, j0 = blockIdx.x * 128;
    int kbase = blockIdx.z * kPerZ;
    int T = kPerZ >> 5;                          // k-tiles of 32

    // ---- loader precompute: 8 chunks/thread ----
    // e = t + i*256; tile = e>>10 (0:A 1:B); idx = e&1023; r = idx>>3; l = idx&7
    // phys = tile*16384 + r*128 + ((l ^ (r&7))<<4)
    // ---- ldmatrix lane precompute ----
    int g = lane >> 3, lr = lane & 7;
    // A role: rows m-local = (g&1)*8 + lr (+ mt*16), chunk = cb + (g>>1)
    int rA = wm * 64 + ((g & 1) << 3) + lr;
    uint32_t aRow = sbase + (uint32_t)rA * 128;
    uint32_t sA = (uint32_t)(rA & 7);
    uint32_t cAoff = (uint32_t)(g >> 1);
    // B role: rows n-local = ((g>>1)<<3) + lr (+ nt*16), chunk = cb + (g&1)
    int rB = wn * 32 + ((g >> 1) << 3) + lr;
    uint32_t bRow = sbase + 16384u + (uint32_t)rB * 128;
    uint32_t sB = (uint32_t)(rB & 7);
    uint32_t cBoff = (uint32_t)(g & 1);

    float acc[4][4][4];
    #pragma unroll
    for (int a = 0; a < 4; a++)
        #pragma unroll
        for (int b = 0; b < 4; b++)
            #pragma unroll
            for (int c = 0; c < 4; c++) acc[a][b][c] = 0.0f;

    // ---- stage loader ----
    auto load_stage = [&](int kt, int buf) {
        int kk = kbase + kt * 32;
        uint32_t dstBase = sbase + (uint32_t)buf * STAGE_BYTES;
        #pragma unroll
        for (int i = 0; i < 8; i++) {
            int e = t + i * 256;
            int tile = e >> 10;
            int idx = e & 1023;
            int r = idx >> 3, l = idx & 7;
            uint32_t phys = dstBase + (uint32_t)tile * 16384u + (uint32_t)r * 128u
                          + (uint32_t)(((l ^ (r & 7)) << 4));
            const __half* srcp;
            int kofs = (l & 3) * 8;
            if (tile == 0) {
                srcp = (l < 4) ? Ah : Al;
                srcp += (size_t)(i0 + r) * ldk + kk + kofs;
            } else {
                srcp = (l < 4) ? Bh : Bl;
                srcp += (size_t)(j0 + r) * ldk + kk + kofs;
            }
            cp16(phys, srcp);
        }
        CP_COMMIT();
    };

    load_stage(0, 0);
    if (T > 1) load_stage(1, 1); else CP_COMMIT();

    for (int kt = 0; kt < T; kt++) {
        CP_WAIT1();
        __syncthreads();
        uint32_t stOff = (uint32_t)(kt & 1) * STAGE_BYTES;

        #pragma unroll
        for (int ks = 0; ks < 2; ks++) {
            uint32_t aH[4][4], aL[4][4], bH[8], bL[8];
            uint32_t cbH = (uint32_t)(ks * 2);          // hi chunks 0..3
            uint32_t cbL = cbH + 4;                     // lo chunks 4..7
            #pragma unroll
            for (int mt = 0; mt < 4; mt++) {
                uint32_t rowa = aRow + stOff + (uint32_t)(mt * 16) * 128u;
                ldsm4(aH[mt], rowa + (((cbH + cAoff) ^ sA) << 4));
                ldsm4(aL[mt], rowa + (((cbL + cAoff) ^ sA) << 4));
            }
            #pragma unroll
            for (int nt = 0; nt < 2; nt++) {
                uint32_t rowb = bRow + stOff + (uint32_t)(nt * 16) * 128u;
                ldsm4(&bH[nt * 4], rowb + (((cbH + cBoff) ^ sB) << 4));
                ldsm4(&bL[nt * 4], rowb + (((cbL + cBoff) ^ sB) << 4));
            }
            #pragma unroll
            for (int mt = 0; mt < 4; mt++) {
                #pragma unroll
                for (int j = 0; j < 4; j++) {
                    mma16816(acc[mt][j], aH[mt], &bH[j * 2]);
                    mma16816(acc[mt][j], aL[mt], &bH[j * 2]);
                    mma16816(acc[mt][j], aH[mt], &bL[j * 2]);
                }
            }
        }
        __syncthreads();
        if (kt + 2 < T) load_stage(kt + 2, kt & 1);
        else CP_COMMIT();
    }

    // ---- epilogue ----
    float* Cz = C + (size_t)blockIdx.z * partStride;
    int qid = lane >> 2, tc = lane & 3;
    #pragma unroll
    for (int mt = 0; mt < 4; mt++) {
        int r0 = i0 + wm * 64 + mt * 16 + qid;
        #pragma unroll
        for (int j = 0; j < 4; j++) {
            int cc = j0 + wn * 32 + j * 8 + tc * 2;
            *(float2*)&Cz[(size_t)r0 * ldc + cc]       = make_float2(acc[mt][j][0], acc[mt][j][1]);
            *(float2*)&Cz[(size_t)(r0 + 8) * ldc + cc] = make_float2(acc[mt][j][2], acc[mt][j][3]);
        }
    }
}

// ---------------- launch ----------------
extern "C" void kernel_launch(void* const* d_in, const int* in_sizes, int n_in,
                              void* d_out, int out_size)
{
    const float* x = (const float*)d_in[0];   // [n, d]
    const float* w = (const float*)d_in[1];   // [d, d]
    float* out = (float*)d_out;               // [n, d]

    int d = (int)(sqrt((double)in_sizes[1]) + 0.5);
    int n = in_sizes[0] / d;

    float *nrm, *Gpart, *Mb;
    __half *nh, *nl, *nTh, *nTl, *xTh, *xTl, *WTh, *WTl, *Gh, *Gl, *MTh, *MTl;
    cudaGetSymbolAddress((void**)&nrm, g_norm);
    cudaGetSymbolAddress((void**)&nh, g_norm_h);   cudaGetSymbolAddress((void**)&nl, g_norm_l);
    cudaGetSymbolAddress((void**)&nTh, g_normT_h); cudaGetSymbolAddress((void**)&nTl, g_normT_l);
    cudaGetSymbolAddress((void**)&xTh, g_xT_h);    cudaGetSymbolAddress((void**)&xTl, g_xT_l);
    cudaGetSymbolAddress((void**)&WTh, g_WT_h);    cudaGetSymbolAddress((void**)&WTl, g_WT_l);
    cudaGetSymbolAddress((void**)&Gpart, g_Gpart);
    cudaGetSymbolAddress((void**)&Gh, g_G_h);      cudaGetSymbolAddress((void**)&Gl, g_G_l);
    cudaGetSymbolAddress((void**)&Mb, g_M);
    cudaGetSymbolAddress((void**)&MTh, g_MT_h);    cudaGetSymbolAddress((void**)&MTl, g_MT_l);

    cudaFuncSetAttribute(k_mma_gemm, cudaFuncAttributeMaxDynamicSharedMemorySize, 2 * STAGE_BYTES);

    dim3 tb(32, 8);

    // 1) normalize + fp16 split
    k_normalize<<<n, 256>>>(x, nrm, nh, nl);
    // 2) transposed splits
    k_tsplit<<<dim3(d / 32, n / 32), tb>>>(nrm, nTh, nTl, n, d);
    k_tsplit<<<dim3(d / 32, n / 32), tb>>>(x, xTh, xTl, n, d);
    k_tsplit<<<dim3(d / 32, d / 32), tb>>>(w, WTh, WTl, d, d);
    // 3) G = norm^T @ x  (K = n, split over ZSPLIT partials)
    k_mma_gemm<<<dim3(d / 128, d / 128, ZSPLIT), 256, 2 * STAGE_BYTES>>>(
        nTh, nTl, xTh, xTl, Gpart, n, n / ZSPLIT, d, d * d);
    k_reduce_split<<<(d * d) / 256, 256>>>(Gpart, Gh, Gl);
    // 4) M = G @ W
    k_mma_gemm<<<dim3(d / 128, d / 128, 1), 256, 2 * STAGE_BYTES>>>(
        Gh, Gl, WTh, WTl, Mb, d, d, d, 0);
    k_tsplit<<<dim3(d / 32, d / 32), tb>>>(Mb, MTh, MTl, d, d);
    // 5) out = norm @ M
    k_mma_gemm<<<dim3(d / 128, n / 128, 1), 256, 2 * STAGE_BYTES>>>(
        nh, nl, MTh, MTl, out, d, d, d, 0);
}

// round 7
// speedup vs baseline: 2.6097x; 1.4943x over previous
#include <cuda_runtime.h>
#include <cuda_fp16.h>
#include <math.h>
#include <stdint.h>

#define NROWS 8192
#define DDIM  1024
#define ZSPLIT 8
#define ZSPLIT2 4

// ---------------- scratch (device globals; no allocation) ----------------
__device__ float  g_norm  [NROWS * DDIM];
__device__ __half g_norm_h[NROWS * DDIM];
__device__ __half g_norm_l[NROWS * DDIM];
__device__ __half g_normT_h[DDIM * NROWS];
__device__ __half g_normT_l[DDIM * NROWS];
__device__ __half g_xT_h  [DDIM * NROWS];
__device__ __half g_xT_l  [DDIM * NROWS];
__device__ __half g_WT_h  [DDIM * DDIM];
__device__ __half g_WT_l  [DDIM * DDIM];
__device__ float  g_Gpart [ZSPLIT * DDIM * DDIM];   // reused for M partials later
__device__ __half g_G_h   [DDIM * DDIM];
__device__ __half g_G_l   [DDIM * DDIM];
__device__ __half g_MT_h  [DDIM * DDIM];
__device__ __half g_MT_l  [DDIM * DDIM];

// ---------------- PTX helpers (plain sm_103-legal subset) ----------------
__device__ __forceinline__ uint32_t smem_u32(const void* p) {
    uint32_t a;
    asm("{ .reg .u64 t; cvta.to.shared.u64 t, %1; cvt.u32.u64 %0, t; }" : "=r"(a) : "l"(p));
    return a;
}
__device__ __forceinline__ void cp16(uint32_t dst, const void* src) {
    asm volatile("cp.async.cg.shared.global [%0], [%1], 16;" :: "r"(dst), "l"(src));
}
#define CP_COMMIT() asm volatile("cp.async.commit_group;" ::: "memory")
#define CP_WAIT1()  asm volatile("cp.async.wait_group 1;" ::: "memory")

__device__ __forceinline__ void ldsm4(uint32_t* r, uint32_t addr) {
    asm volatile("ldmatrix.sync.aligned.m8n8.x4.shared.b16 {%0,%1,%2,%3}, [%4];"
                 : "=r"(r[0]), "=r"(r[1]), "=r"(r[2]), "=r"(r[3]) : "r"(addr));
}
// fp32-accumulate MMA (hi term)
__device__ __forceinline__ void mma16816(float* c, const uint32_t* a, const uint32_t* b) {
    asm volatile(
        "mma.sync.aligned.m16n8k16.row.col.f32.f16.f16.f32 "
        "{%0,%1,%2,%3}, {%4,%5,%6,%7}, {%8,%9}, {%0,%1,%2,%3};"
        : "+f"(c[0]), "+f"(c[1]), "+f"(c[2]), "+f"(c[3])
        : "r"(a[0]), "r"(a[1]), "r"(a[2]), "r"(a[3]), "r"(b[0]), "r"(b[1]));
}
// fp16-accumulate MMA (correction terms; full-rate)
__device__ __forceinline__ void mma16816_f16(uint32_t* c, const uint32_t* a, const uint32_t* b) {
    asm volatile(
        "mma.sync.aligned.m16n8k16.row.col.f16.f16.f16.f16 "
        "{%0,%1}, {%2,%3,%4,%5}, {%6,%7}, {%0,%1};"
        : "+r"(c[0]), "+r"(c[1])
        : "r"(a[0]), "r"(a[1]), "r"(a[2]), "r"(a[3]), "r"(b[0]), "r"(b[1]));
}

// ---------------- tiny helper kernels ----------------
__global__ void k_nop() {}

__global__ void k_normalize(const float* __restrict__ x, float* __restrict__ nrm,
                            __half* __restrict__ nh, __half* __restrict__ nl) {
    int row = blockIdx.x;
    const float4* xr = (const float4*)(x + (size_t)row * DDIM);
    float4 v = xr[threadIdx.x];
    float s = v.x * v.x + v.y * v.y + v.z * v.z + v.w * v.w;
    #pragma unroll
    for (int o = 16; o > 0; o >>= 1) s += __shfl_xor_sync(0xffffffffu, s, o);
    __shared__ float red[8];
    int lane = threadIdx.x & 31, wid = threadIdx.x >> 5;
    if (lane == 0) red[wid] = s;
    __syncthreads();
    if (wid == 0) {
        float t = (lane < 8) ? red[lane] : 0.0f;
        #pragma unroll
        for (int o = 4; o > 0; o >>= 1) t += __shfl_xor_sync(0xffffffffu, t, o);
        if (lane == 0) red[0] = t;
    }
    __syncthreads();
    float inv = 1.0f / fmaxf(sqrtf(red[0]), 1e-12f);
    v.x *= inv; v.y *= inv; v.z *= inv; v.w *= inv;
    ((float4*)(nrm + (size_t)row * DDIM))[threadIdx.x] = v;
    size_t base = (size_t)row * DDIM + threadIdx.x * 4;
    float vv[4] = {v.x, v.y, v.z, v.w};
    #pragma unroll
    for (int j = 0; j < 4; j++) {
        __half h = __float2half_rn(vv[j]);
        nh[base + j] = h;
        nl[base + j] = __float2half_rn(vv[j] - __half2float(h));
    }
}

// transpose + split: src[R,C] fp32 -> dst[C,R] fp16 hi/lo
__global__ void k_tsplit(const float* __restrict__ src,
                         __half* __restrict__ dh, __half* __restrict__ dl,
                         int R, int C) {
    __shared__ float tile[32][33];
    int c0 = blockIdx.x * 32, r0 = blockIdx.y * 32;
    #pragma unroll
    for (int i = threadIdx.y; i < 32; i += 8)
        tile[i][threadIdx.x] = src[(size_t)(r0 + i) * C + c0 + threadIdx.x];
    __syncthreads();
    #pragma unroll
    for (int i = threadIdx.y; i < 32; i += 8) {
        float v = tile[threadIdx.x][i];
        __half h = __float2half_rn(v);
        size_t o = (size_t)(c0 + i) * R + r0 + threadIdx.x;
        dh[o] = h;
        dl[o] = __float2half_rn(v - __half2float(h));
    }
}

// reduce ZSPLIT partials + split (no transpose) — for G
__global__ void k_reduce_split(const float* __restrict__ p,
                               __half* __restrict__ dh, __half* __restrict__ dl) {
    int i = blockIdx.x * blockDim.x + threadIdx.x;
    const int n = DDIM * DDIM;
    float s = 0.0f;
    #pragma unroll
    for (int z = 0; z < ZSPLIT; z++) s += p[i + z * n];
    __half h = __float2half_rn(s);
    dh[i] = h;
    dl[i] = __float2half_rn(s - __half2float(h));
}

// reduce ZSPLIT2 partials of M + TRANSPOSE + split -> MT hi/lo
__global__ void k_reduce_tsplit(const float* __restrict__ p,
                                __half* __restrict__ dh, __half* __restrict__ dl) {
    __shared__ float tile[32][33];
    const int n = DDIM * DDIM;
    int c0 = blockIdx.x * 32, r0 = blockIdx.y * 32;
    #pragma unroll
    for (int i = threadIdx.y; i < 32; i += 8) {
        size_t o = (size_t)(r0 + i) * DDIM + c0 + threadIdx.x;
        float s = 0.0f;
        #pragma unroll
        for (int z = 0; z < ZSPLIT2; z++) s += p[o + (size_t)z * n];
        tile[i][threadIdx.x] = s;
    }
    __syncthreads();
    #pragma unroll
    for (int i = threadIdx.y; i < 32; i += 8) {
        float v = tile[threadIdx.x][i];
        __half h = __float2half_rn(v);
        size_t o = (size_t)(c0 + i) * DDIM + r0 + threadIdx.x;
        dh[o] = h;
        dl[o] = __float2half_rn(v - __half2float(h));
    }
}

// ---------------- fp16x3 HMMA GEMM: C[i,j] = sum_k A[i,k]*B[j,k] ----------------
// hi term: f32 acc; correction terms (AlBh + AhBl): shared f16 acc (full-rate).
#define STAGE_BYTES 32768

__global__ __launch_bounds__(256) void k_mma_gemm(
    const __half* __restrict__ Ah, const __half* __restrict__ Al,
    const __half* __restrict__ Bh, const __half* __restrict__ Bl,
    float* __restrict__ C, int ldk, int kPerZ, int ldc, int partStride)
{
    extern __shared__ char smem[];
    uint32_t sbase = smem_u32(smem);
    int t = threadIdx.x;
    int lane = t & 31, w = t >> 5;
    int wm = w >> 2, wn = w & 3;                 // warp grid 2 x 4
    int i0 = blockIdx.y * 128, j0 = blockIdx.x * 128;
    int kbase = blockIdx.z * kPerZ;
    int T = kPerZ >> 5;                          // k-tiles of 32

    int g = lane >> 3, lr = lane & 7;
    int rA = wm * 64 + ((g & 1) << 3) + lr;
    uint32_t aRow = sbase + (uint32_t)rA * 128;
    uint32_t sA = (uint32_t)(rA & 7);
    uint32_t cAoff = (uint32_t)(g >> 1);
    int rB = wn * 32 + ((g >> 1) << 3) + lr;
    uint32_t bRow = sbase + 16384u + (uint32_t)rB * 128;
    uint32_t sB = (uint32_t)(rB & 7);
    uint32_t cBoff = (uint32_t)(g & 1);

    float acc[4][4][4];
    uint32_t corr[4][4][2];
    #pragma unroll
    for (int a = 0; a < 4; a++)
        #pragma unroll
        for (int b = 0; b < 4; b++) {
            #pragma unroll
            for (int c = 0; c < 4; c++) acc[a][b][c] = 0.0f;
            corr[a][b][0] = 0u; corr[a][b][1] = 0u;
        }

    auto load_stage = [&](int kt, int buf) {
        int kk = kbase + kt * 32;
        uint32_t dstBase = sbase + (uint32_t)buf * STAGE_BYTES;
        #pragma unroll
        for (int i = 0; i < 8; i++) {
            int e = t + i * 256;
            int tile = e >> 10;
            int idx = e & 1023;
            int r = idx >> 3, l = idx & 7;
            uint32_t phys = dstBase + (uint32_t)tile * 16384u + (uint32_t)r * 128u
                          + (uint32_t)(((l ^ (r & 7)) << 4));
            const __half* srcp;
            int kofs = (l & 3) * 8;
            if (tile == 0) {
                srcp = (l < 4) ? Ah : Al;
                srcp += (size_t)(i0 + r) * ldk + kk + kofs;
            } else {
                srcp = (l < 4) ? Bh : Bl;
                srcp += (size_t)(j0 + r) * ldk + kk + kofs;
            }
            cp16(phys, srcp);
        }
        CP_COMMIT();
    };

    load_stage(0, 0);
    if (T > 1) load_stage(1, 1); else CP_COMMIT();

    for (int kt = 0; kt < T; kt++) {
        CP_WAIT1();
        __syncthreads();
        uint32_t stOff = (uint32_t)(kt & 1) * STAGE_BYTES;

        #pragma unroll
        for (int ks = 0; ks < 2; ks++) {
            uint32_t aH[4][4], aL[4][4], bH[8], bL[8];
            uint32_t cbH = (uint32_t)(ks * 2);
            uint32_t cbL = cbH + 4;
            #pragma unroll
            for (int mt = 0; mt < 4; mt++) {
                uint32_t rowa = aRow + stOff + (uint32_t)(mt * 16) * 128u;
                ldsm4(aH[mt], rowa + (((cbH + cAoff) ^ sA) << 4));
                ldsm4(aL[mt], rowa + (((cbL + cAoff) ^ sA) << 4));
            }
            #pragma unroll
            for (int nt = 0; nt < 2; nt++) {
                uint32_t rowb = bRow + stOff + (uint32_t)(nt * 16) * 128u;
                ldsm4(&bH[nt * 4], rowb + (((cbH + cBoff) ^ sB) << 4));
                ldsm4(&bL[nt * 4], rowb + (((cbL + cBoff) ^ sB) << 4));
            }
            #pragma unroll
            for (int mt = 0; mt < 4; mt++) {
                #pragma unroll
                for (int j = 0; j < 4; j++) {
                    mma16816(acc[mt][j], aH[mt], &bH[j * 2]);
                    mma16816_f16(corr[mt][j], aL[mt], &bH[j * 2]);
                    mma16816_f16(corr[mt][j], aH[mt], &bL[j * 2]);
                }
            }
        }
        __syncthreads();
        if (kt + 2 < T) load_stage(kt + 2, kt & 1);
        else CP_COMMIT();
    }

    // ---- epilogue: merge f16 corrections into f32 accums ----
    float* Cz = C + (size_t)blockIdx.z * partStride;
    int qid = lane >> 2, tc = lane & 3;
    #pragma unroll
    for (int mt = 0; mt < 4; mt++) {
        int r0 = i0 + wm * 64 + mt * 16 + qid;
        #pragma unroll
        for (int j = 0; j < 4; j++) {
            __half2 p0 = *(__half2*)&corr[mt][j][0];   // elems 0,1
            __half2 p1 = *(__half2*)&corr[mt][j][1];   // elems 2,3
            int cc = j0 + wn * 32 + j * 8 + tc * 2;
            *(float2*)&Cz[(size_t)r0 * ldc + cc] =
                make_float2(acc[mt][j][0] + __half2float(p0.x),
                            acc[mt][j][1] + __half2float(p0.y));
            *(float2*)&Cz[(size_t)(r0 + 8) * ldc + cc] =
                make_float2(acc[mt][j][2] + __half2float(p1.x),
                            acc[mt][j][3] + __half2float(p1.y));
        }
    }
}

// ---------------- launch ----------------
extern "C" void kernel_launch(void* const* d_in, const int* in_sizes, int n_in,
                              void* d_out, int out_size)
{
    const float* x = (const float*)d_in[0];   // [n, d]
    const float* w = (const float*)d_in[1];   // [d, d]
    float* out = (float*)d_out;               // [n, d]

    int d = (int)(sqrt((double)in_sizes[1]) + 0.5);
    int n = in_sizes[0] / d;

    float *nrm, *Gpart;
    __half *nh, *nl, *nTh, *nTl, *xTh, *xTl, *WTh, *WTl, *Gh, *Gl, *MTh, *MTl;
    cudaGetSymbolAddress((void**)&nrm, g_norm);
    cudaGetSymbolAddress((void**)&nh, g_norm_h);   cudaGetSymbolAddress((void**)&nl, g_norm_l);
    cudaGetSymbolAddress((void**)&nTh, g_normT_h); cudaGetSymbolAddress((void**)&nTl, g_normT_l);
    cudaGetSymbolAddress((void**)&xTh, g_xT_h);    cudaGetSymbolAddress((void**)&xTl, g_xT_l);
    cudaGetSymbolAddress((void**)&WTh, g_WT_h);    cudaGetSymbolAddress((void**)&WTl, g_WT_l);
    cudaGetSymbolAddress((void**)&Gpart, g_Gpart);
    cudaGetSymbolAddress((void**)&Gh, g_G_h);      cudaGetSymbolAddress((void**)&Gl, g_G_l);
    cudaGetSymbolAddress((void**)&MTh, g_MT_h);    cudaGetSymbolAddress((void**)&MTl, g_MT_l);

    cudaFuncSetAttribute(k_mma_gemm, cudaFuncAttributeMaxDynamicSharedMemorySize, 2 * STAGE_BYTES);

    dim3 tb(32, 8);

    // idx 0: normalize + fp16 split
    k_normalize<<<n, 256>>>(x, nrm, nh, nl);
    // idx 1-3: transposed splits
    k_tsplit<<<dim3(d / 32, n / 32), tb>>>(nrm, nTh, nTl, n, d);
    k_tsplit<<<dim3(d / 32, n / 32), tb>>>(x, xTh, xTl, n, d);
    k_tsplit<<<dim3(d / 32, d / 32), tb>>>(w, WTh, WTl, d, d);
    // idx 4: nop (aligns big GEMM to ncu's -s 5 capture slot)
    k_nop<<<1, 1>>>();
    // idx 5: G = norm^T @ x  (K = n, ZSPLIT partials)
    k_mma_gemm<<<dim3(d / 128, d / 128, ZSPLIT), 256, 2 * STAGE_BYTES>>>(
        nTh, nTl, xTh, xTl, Gpart, n, n / ZSPLIT, d, d * d);
    // idx 6: reduce G partials + split
    k_reduce_split<<<(d * d) / 256, 256>>>(Gpart, Gh, Gl);
    // idx 7: M partials = G @ W (K split by ZSPLIT2; reuse Gpart as scratch)
    k_mma_gemm<<<dim3(d / 128, d / 128, ZSPLIT2), 256, 2 * STAGE_BYTES>>>(
        Gh, Gl, WTh, WTl, Gpart, d, d / ZSPLIT2, d, d * d);
    // idx 8: reduce M partials + transpose + split
    k_reduce_tsplit<<<dim3(d / 32, d / 32), tb>>>(Gpart, MTh, MTl);
    // idx 9: out = norm @ M
    k_mma_gemm<<<dim3(d / 128, n / 128, 1), 256, 2 * STAGE_BYTES>>>(
        nh, nl, MTh, MTl, out, d, d, d, 0);
}

// round 8
// speedup vs baseline: 3.2157x; 1.2322x over previous
#include <cuda_runtime.h>
#include <cuda_fp16.h>
#include <math.h>
#include <stdint.h>

#define NROWS 8192
#define DDIM  1024
#define ZSPLIT 8
#define ZSPLIT2 4

// ---------------- scratch (device globals; no allocation) ----------------
__device__ float  g_norm  [NROWS * DDIM];
__device__ __half g_norm_h[NROWS * DDIM];
__device__ __half g_norm_l[NROWS * DDIM];
__device__ __half g_normT_h[DDIM * NROWS];
__device__ __half g_normT_l[DDIM * NROWS];
__device__ __half g_xT_h  [DDIM * NROWS];
__device__ __half g_xT_l  [DDIM * NROWS];
__device__ __half g_WT_h  [DDIM * DDIM];
__device__ __half g_WT_l  [DDIM * DDIM];
__device__ float  g_Gpart [ZSPLIT * DDIM * DDIM];   // reused for M partials later
__device__ __half g_G_h   [DDIM * DDIM];
__device__ __half g_G_l   [DDIM * DDIM];
__device__ __half g_MT_h  [DDIM * DDIM];
__device__ __half g_MT_l  [DDIM * DDIM];

// ---------------- PTX helpers (plain sm_103-legal subset) ----------------
__device__ __forceinline__ uint32_t smem_u32(const void* p) {
    uint32_t a;
    asm("{ .reg .u64 t; cvta.to.shared.u64 t, %1; cvt.u32.u64 %0, t; }" : "=r"(a) : "l"(p));
    return a;
}
__device__ __forceinline__ void cp16(uint32_t dst, const void* src) {
    asm volatile("cp.async.cg.shared.global [%0], [%1], 16;" :: "r"(dst), "l"(src));
}
#define CP_COMMIT() asm volatile("cp.async.commit_group;" ::: "memory")
#define CP_WAIT1()  asm volatile("cp.async.wait_group 1;" ::: "memory")

__device__ __forceinline__ void ldsm4(uint32_t* r, uint32_t addr) {
    asm volatile("ldmatrix.sync.aligned.m8n8.x4.shared.b16 {%0,%1,%2,%3}, [%4];"
                 : "=r"(r[0]), "=r"(r[1]), "=r"(r[2]), "=r"(r[3]) : "r"(addr));
}
// fp32-accumulate MMA (hi term)
__device__ __forceinline__ void mma16816(float* c, const uint32_t* a, const uint32_t* b) {
    asm volatile(
        "mma.sync.aligned.m16n8k16.row.col.f32.f16.f16.f32 "
        "{%0,%1,%2,%3}, {%4,%5,%6,%7}, {%8,%9}, {%0,%1,%2,%3};"
        : "+f"(c[0]), "+f"(c[1]), "+f"(c[2]), "+f"(c[3])
        : "r"(a[0]), "r"(a[1]), "r"(a[2]), "r"(a[3]), "r"(b[0]), "r"(b[1]));
}
// fp16-accumulate MMA (correction terms; full-rate)
__device__ __forceinline__ void mma16816_f16(uint32_t* c, const uint32_t* a, const uint32_t* b) {
    asm volatile(
        "mma.sync.aligned.m16n8k16.row.col.f16.f16.f16.f16 "
        "{%0,%1}, {%2,%3,%4,%5}, {%6,%7}, {%0,%1};"
        : "+r"(c[0]), "+r"(c[1])
        : "r"(a[0]), "r"(a[1]), "r"(a[2]), "r"(a[3]), "r"(b[0]), "r"(b[1]));
}

// ---------------- tiny helper kernels ----------------
__global__ void k_nop() {}

__global__ void k_normalize(const float* __restrict__ x, float* __restrict__ nrm,
                            __half* __restrict__ nh, __half* __restrict__ nl) {
    int row = blockIdx.x;
    const float4* xr = (const float4*)(x + (size_t)row * DDIM);
    float4 v = xr[threadIdx.x];
    float s = v.x * v.x + v.y * v.y + v.z * v.z + v.w * v.w;
    #pragma unroll
    for (int o = 16; o > 0; o >>= 1) s += __shfl_xor_sync(0xffffffffu, s, o);
    __shared__ float red[8];
    int lane = threadIdx.x & 31, wid = threadIdx.x >> 5;
    if (lane == 0) red[wid] = s;
    __syncthreads();
    if (wid == 0) {
        float t = (lane < 8) ? red[lane] : 0.0f;
        #pragma unroll
        for (int o = 4; o > 0; o >>= 1) t += __shfl_xor_sync(0xffffffffu, t, o);
        if (lane == 0) red[0] = t;
    }
    __syncthreads();
    float inv = 1.0f / fmaxf(sqrtf(red[0]), 1e-12f);
    v.x *= inv; v.y *= inv; v.z *= inv; v.w *= inv;
    ((float4*)(nrm + (size_t)row * DDIM))[threadIdx.x] = v;
    size_t base = (size_t)row * DDIM + threadIdx.x * 4;
    float vv[4] = {v.x, v.y, v.z, v.w};
    #pragma unroll
    for (int j = 0; j < 4; j++) {
        __half h = __float2half_rn(vv[j]);
        nh[base + j] = h;
        nl[base + j] = __float2half_rn(vv[j] - __half2float(h));
    }
}

// transpose + split: src[R,C] fp32 -> dst[C,R] fp16 hi/lo
__global__ void k_tsplit(const float* __restrict__ src,
                         __half* __restrict__ dh, __half* __restrict__ dl,
                         int R, int C) {
    __shared__ float tile[32][33];
    int c0 = blockIdx.x * 32, r0 = blockIdx.y * 32;
    #pragma unroll
    for (int i = threadIdx.y; i < 32; i += 8)
        tile[i][threadIdx.x] = src[(size_t)(r0 + i) * C + c0 + threadIdx.x];
    __syncthreads();
    #pragma unroll
    for (int i = threadIdx.y; i < 32; i += 8) {
        float v = tile[threadIdx.x][i];
        __half h = __float2half_rn(v);
        size_t o = (size_t)(c0 + i) * R + r0 + threadIdx.x;
        dh[o] = h;
        dl[o] = __float2half_rn(v - __half2float(h));
    }
}

// reduce ZSPLIT partials + split, exploiting G symmetry:
// only 128x128 blocks with row_blk <= col_blk were computed; mirror the rest.
__global__ void k_reduce_split_sym(const float* __restrict__ p,
                                   __half* __restrict__ dh, __half* __restrict__ dl) {
    const int n = DDIM * DDIM;
    int c0 = blockIdx.x * 32, r0 = blockIdx.y * 32;
    if ((blockIdx.y >> 2) <= (blockIdx.x >> 2)) {
        // upper (computed) region: direct
        #pragma unroll
        for (int i = threadIdx.y; i < 32; i += 8) {
            size_t o = (size_t)(r0 + i) * DDIM + c0 + threadIdx.x;
            float s = 0.0f;
            #pragma unroll
            for (int z = 0; z < ZSPLIT; z++) s += p[o + (size_t)z * n];
            __half h = __float2half_rn(s);
            dh[o] = h;
            dl[o] = __float2half_rn(s - __half2float(h));
        }
    } else {
        // lower region: read mirrored upper tile (coalesced), transpose via smem
        __shared__ float tile[32][33];
        #pragma unroll
        for (int i = threadIdx.y; i < 32; i += 8) {
            size_t o = (size_t)(c0 + i) * DDIM + r0 + threadIdx.x;
            float s = 0.0f;
            #pragma unroll
            for (int z = 0; z < ZSPLIT; z++) s += p[o + (size_t)z * n];
            tile[i][threadIdx.x] = s;
        }
        __syncthreads();
        #pragma unroll
        for (int i = threadIdx.y; i < 32; i += 8) {
            float v = tile[threadIdx.x][i];
            size_t o = (size_t)(r0 + i) * DDIM + c0 + threadIdx.x;
            __half h = __float2half_rn(v);
            dh[o] = h;
            dl[o] = __float2half_rn(v - __half2float(h));
        }
    }
}

// reduce ZSPLIT2 partials of M + TRANSPOSE + split -> MT hi/lo
__global__ void k_reduce_tsplit(const float* __restrict__ p,
                                __half* __restrict__ dh, __half* __restrict__ dl) {
    __shared__ float tile[32][33];
    const int n = DDIM * DDIM;
    int c0 = blockIdx.x * 32, r0 = blockIdx.y * 32;
    #pragma unroll
    for (int i = threadIdx.y; i < 32; i += 8) {
        size_t o = (size_t)(r0 + i) * DDIM + c0 + threadIdx.x;
        float s = 0.0f;
        #pragma unroll
        for (int z = 0; z < ZSPLIT2; z++) s += p[o + (size_t)z * n];
        tile[i][threadIdx.x] = s;
    }
    __syncthreads();
    #pragma unroll
    for (int i = threadIdx.y; i < 32; i += 8) {
        float v = tile[threadIdx.x][i];
        __half h = __float2half_rn(v);
        size_t o = (size_t)(c0 + i) * DDIM + r0 + threadIdx.x;
        dh[o] = h;
        dl[o] = __float2half_rn(v - __half2float(h));
    }
}

// ---------------- fp16x3 HMMA GEMM: C[i,j] = sum_k A[i,k]*B[j,k] ----------------
// hi term: f32 acc; correction terms (AlBh + AhBl): shared f16 acc (full-rate).
// symUpper != 0: skip blocks with row_blk > col_blk (output known symmetric).
#define STAGE_BYTES 32768

__global__ __launch_bounds__(256) void k_mma_gemm(
    const __half* __restrict__ Ah, const __half* __restrict__ Al,
    const __half* __restrict__ Bh, const __half* __restrict__ Bl,
    float* __restrict__ C, int ldk, int kPerZ, int ldc, int partStride, int symUpper)
{
    if (symUpper && blockIdx.y > blockIdx.x) return;

    extern __shared__ char smem[];
    uint32_t sbase = smem_u32(smem);
    int t = threadIdx.x;
    int lane = t & 31, w = t >> 5;
    int wm = w >> 2, wn = w & 3;                 // warp grid 2 x 4
    int i0 = blockIdx.y * 128, j0 = blockIdx.x * 128;
    int kbase = blockIdx.z * kPerZ;
    int T = kPerZ >> 5;                          // k-tiles of 32

    int g = lane >> 3, lr = lane & 7;
    int rA = wm * 64 + ((g & 1) << 3) + lr;
    uint32_t aRow = sbase + (uint32_t)rA * 128;
    uint32_t sA = (uint32_t)(rA & 7);
    uint32_t cAoff = (uint32_t)(g >> 1);
    int rB = wn * 32 + ((g >> 1) << 3) + lr;
    uint32_t bRow = sbase + 16384u + (uint32_t)rB * 128;
    uint32_t sB = (uint32_t)(rB & 7);
    uint32_t cBoff = (uint32_t)(g & 1);

    float acc[4][4][4];
    uint32_t corr[4][4][2];
    #pragma unroll
    for (int a = 0; a < 4; a++)
        #pragma unroll
        for (int b = 0; b < 4; b++) {
            #pragma unroll
            for (int c = 0; c < 4; c++) acc[a][b][c] = 0.0f;
            corr[a][b][0] = 0u; corr[a][b][1] = 0u;
        }

    auto load_stage = [&](int kt, int buf) {
        int kk = kbase + kt * 32;
        uint32_t dstBase = sbase + (uint32_t)buf * STAGE_BYTES;
        #pragma unroll
        for (int i = 0; i < 8; i++) {
            int e = t + i * 256;
            int tile = e >> 10;
            int idx = e & 1023;
            int r = idx >> 3, l = idx & 7;
            uint32_t phys = dstBase + (uint32_t)tile * 16384u + (uint32_t)r * 128u
                          + (uint32_t)(((l ^ (r & 7)) << 4));
            const __half* srcp;
            int kofs = (l & 3) * 8;
            if (tile == 0) {
                srcp = (l < 4) ? Ah : Al;
                srcp += (size_t)(i0 + r) * ldk + kk + kofs;
            } else {
                srcp = (l < 4) ? Bh : Bl;
                srcp += (size_t)(j0 + r) * ldk + kk + kofs;
            }
            cp16(phys, srcp);
        }
        CP_COMMIT();
    };

    load_stage(0, 0);
    if (T > 1) load_stage(1, 1); else CP_COMMIT();

    for (int kt = 0; kt < T; kt++) {
        CP_WAIT1();
        __syncthreads();
        uint32_t stOff = (uint32_t)(kt & 1) * STAGE_BYTES;

        #pragma unroll
        for (int ks = 0; ks < 2; ks++) {
            uint32_t aH[4][4], aL[4][4], bH[8], bL[8];
            uint32_t cbH = (uint32_t)(ks * 2);
            uint32_t cbL = cbH + 4;
            #pragma unroll
            for (int mt = 0; mt < 4; mt++) {
                uint32_t rowa = aRow + stOff + (uint32_t)(mt * 16) * 128u;
                ldsm4(aH[mt], rowa + (((cbH + cAoff) ^ sA) << 4));
                ldsm4(aL[mt], rowa + (((cbL + cAoff) ^ sA) << 4));
            }
            #pragma unroll
            for (int nt = 0; nt < 2; nt++) {
                uint32_t rowb = bRow + stOff + (uint32_t)(nt * 16) * 128u;
                ldsm4(&bH[nt * 4], rowb + (((cbH + cBoff) ^ sB) << 4));
                ldsm4(&bL[nt * 4], rowb + (((cbL + cBoff) ^ sB) << 4));
            }
            #pragma unroll
            for (int mt = 0; mt < 4; mt++) {
                #pragma unroll
                for (int j = 0; j < 4; j++) {
                    mma16816(acc[mt][j], aH[mt], &bH[j * 2]);
                    mma16816_f16(corr[mt][j], aL[mt], &bH[j * 2]);
                    mma16816_f16(corr[mt][j], aH[mt], &bL[j * 2]);
                }
            }
        }
        __syncthreads();
        if (kt + 2 < T) load_stage(kt + 2, kt & 1);
        else CP_COMMIT();
    }

    // ---- epilogue: merge f16 corrections into f32 accums ----
    float* Cz = C + (size_t)blockIdx.z * partStride;
    int qid = lane >> 2, tc = lane & 3;
    #pragma unroll
    for (int mt = 0; mt < 4; mt++) {
        int r0 = i0 + wm * 64 + mt * 16 + qid;
        #pragma unroll
        for (int j = 0; j < 4; j++) {
            __half2 p0 = *(__half2*)&corr[mt][j][0];   // elems 0,1
            __half2 p1 = *(__half2*)&corr[mt][j][1];   // elems 2,3
            int cc = j0 + wn * 32 + j * 8 + tc * 2;
            *(float2*)&Cz[(size_t)r0 * ldc + cc] =
                make_float2(acc[mt][j][0] + __half2float(p0.x),
                            acc[mt][j][1] + __half2float(p0.y));
            *(float2*)&Cz[(size_t)(r0 + 8) * ldc + cc] =
                make_float2(acc[mt][j][2] + __half2float(p1.x),
                            acc[mt][j][3] + __half2float(p1.y));
        }
    }
}

// ---------------- launch ----------------
extern "C" void kernel_launch(void* const* d_in, const int* in_sizes, int n_in,
                              void* d_out, int out_size)
{
    const float* x = (const float*)d_in[0];   // [n, d]
    const float* w = (const float*)d_in[1];   // [d, d]
    float* out = (float*)d_out;               // [n, d]

    int d = (int)(sqrt((double)in_sizes[1]) + 0.5);
    int n = in_sizes[0] / d;

    float *nrm, *Gpart;
    __half *nh, *nl, *nTh, *nTl, *xTh, *xTl, *WTh, *WTl, *Gh, *Gl, *MTh, *MTl;
    cudaGetSymbolAddress((void**)&nrm, g_norm);
    cudaGetSymbolAddress((void**)&nh, g_norm_h);   cudaGetSymbolAddress((void**)&nl, g_norm_l);
    cudaGetSymbolAddress((void**)&nTh, g_normT_h); cudaGetSymbolAddress((void**)&nTl, g_normT_l);
    cudaGetSymbolAddress((void**)&xTh, g_xT_h);    cudaGetSymbolAddress((void**)&xTl, g_xT_l);
    cudaGetSymbolAddress((void**)&WTh, g_WT_h);    cudaGetSymbolAddress((void**)&WTl, g_WT_l);
    cudaGetSymbolAddress((void**)&Gpart, g_Gpart);
    cudaGetSymbolAddress((void**)&Gh, g_G_h);      cudaGetSymbolAddress((void**)&Gl, g_G_l);
    cudaGetSymbolAddress((void**)&MTh, g_MT_h);    cudaGetSymbolAddress((void**)&MTl, g_MT_l);

    cudaFuncSetAttribute(k_mma_gemm, cudaFuncAttributeMaxDynamicSharedMemorySize, 2 * STAGE_BYTES);

    dim3 tb(32, 8);

    // idx 0: normalize + fp16 split
    k_normalize<<<n, 256>>>(x, nrm, nh, nl);
    // idx 1-3: transposed splits
    k_tsplit<<<dim3(d / 32, n / 32), tb>>>(nrm, nTh, nTl, n, d);
    k_tsplit<<<dim3(d / 32, n / 32), tb>>>(x, xTh, xTl, n, d);
    k_tsplit<<<dim3(d / 32, d / 32), tb>>>(w, WTh, WTl, d, d);
    // idx 4: nop
    k_nop<<<1, 1>>>();
    // idx 5: G = norm^T @ x  (K = n, ZSPLIT partials) — upper-triangular blocks only
    k_mma_gemm<<<dim3(d / 128, d / 128, ZSPLIT), 256, 2 * STAGE_BYTES>>>(
        nTh, nTl, xTh, xTl, Gpart, n, n / ZSPLIT, d, d * d, 1);
    // idx 6: reduce G partials + mirror lower triangle + split
    k_reduce_split_sym<<<dim3(d / 32, d / 32), tb>>>(Gpart, Gh, Gl);
    // idx 7: M partials = G @ W (K split by ZSPLIT2; reuse Gpart as scratch)
    k_mma_gemm<<<dim3(d / 128, d / 128, ZSPLIT2), 256, 2 * STAGE_BYTES>>>(
        Gh, Gl, WTh, WTl, Gpart, d, d / ZSPLIT2, d, d * d, 0);
    // idx 8: reduce M partials + transpose + split
    k_reduce_tsplit<<<dim3(d / 32, d / 32), tb>>>(Gpart, MTh, MTl);
    // idx 9: out = norm @ M
    k_mma_gemm<<<dim3(d / 128, n / 128, 1), 256, 2 * STAGE_BYTES>>>(
        nh, nl, MTh, MTl, out, d, d, d, 0, 0);
}

// round 9
// speedup vs baseline: 3.3823x; 1.0518x over previous
#include <cuda_runtime.h>
#include <cuda_fp16.h>
#include <math.h>
#include <stdint.h>

#define NROWS 8192
#define DDIM  1024
#define ZSPLIT 8
#define ZSPLIT2 4

// ---------------- scratch (device globals; no allocation) ----------------
__device__ float  g_invs  [NROWS];
__device__ __half g_norm_h[NROWS * DDIM];
__device__ __half g_norm_l[NROWS * DDIM];
__device__ __half g_normT_h[DDIM * NROWS];
__device__ __half g_normT_l[DDIM * NROWS];
__device__ __half g_xT_h  [DDIM * NROWS];
__device__ __half g_xT_l  [DDIM * NROWS];
__device__ __half g_WT_h  [DDIM * DDIM];
__device__ __half g_WT_l  [DDIM * DDIM];
__device__ float  g_Gpart [ZSPLIT * DDIM * DDIM];   // reused for M partials later
__device__ __half g_G_h   [DDIM * DDIM];
__device__ __half g_G_l   [DDIM * DDIM];
__device__ __half g_MT_h  [DDIM * DDIM];
__device__ __half g_MT_l  [DDIM * DDIM];

// ---------------- PTX helpers (plain sm_103-legal subset) ----------------
__device__ __forceinline__ uint32_t smem_u32(const void* p) {
    uint32_t a;
    asm("{ .reg .u64 t; cvta.to.shared.u64 t, %1; cvt.u32.u64 %0, t; }" : "=r"(a) : "l"(p));
    return a;
}
__device__ __forceinline__ void cp16(uint32_t dst, const void* src) {
    asm volatile("cp.async.cg.shared.global [%0], [%1], 16;" :: "r"(dst), "l"(src));
}
#define CP_COMMIT() asm volatile("cp.async.commit_group;" ::: "memory")
#define CP_WAIT2()  asm volatile("cp.async.wait_group 2;" ::: "memory")

__device__ __forceinline__ void ldsm4(uint32_t* r, uint32_t addr) {
    asm volatile("ldmatrix.sync.aligned.m8n8.x4.shared.b16 {%0,%1,%2,%3}, [%4];"
                 : "=r"(r[0]), "=r"(r[1]), "=r"(r[2]), "=r"(r[3]) : "r"(addr));
}
// fp32-accumulate MMA (hi term)
__device__ __forceinline__ void mma16816(float* c, const uint32_t* a, const uint32_t* b) {
    asm volatile(
        "mma.sync.aligned.m16n8k16.row.col.f32.f16.f16.f32 "
        "{%0,%1,%2,%3}, {%4,%5,%6,%7}, {%8,%9}, {%0,%1,%2,%3};"
        : "+f"(c[0]), "+f"(c[1]), "+f"(c[2]), "+f"(c[3])
        : "r"(a[0]), "r"(a[1]), "r"(a[2]), "r"(a[3]), "r"(b[0]), "r"(b[1]));
}
// fp16-accumulate MMA (correction terms; full-rate)
__device__ __forceinline__ void mma16816_f16(uint32_t* c, const uint32_t* a, const uint32_t* b) {
    asm volatile(
        "mma.sync.aligned.m16n8k16.row.col.f16.f16.f16.f16 "
        "{%0,%1}, {%2,%3,%4,%5}, {%6,%7}, {%0,%1};"
        : "+r"(c[0]), "+r"(c[1])
        : "r"(a[0]), "r"(a[1]), "r"(a[2]), "r"(a[3]), "r"(b[0]), "r"(b[1]));
}

// ---------------- prep kernels ----------------
// one warp per row: invs[row] = 1 / max(||x_row||, eps)
__global__ void k_rownorm(const float* __restrict__ x, float* __restrict__ invs) {
    int wid = threadIdx.x >> 5, lane = threadIdx.x & 31;
    int row = blockIdx.x * 8 + wid;
    const float4* xr = (const float4*)(x + (size_t)row * DDIM);
    float s = 0.0f;
    #pragma unroll
    for (int j = 0; j < 8; j++) {
        float4 v = xr[lane + 32 * j];
        s += v.x * v.x + v.y * v.y + v.z * v.z + v.w * v.w;
    }
    #pragma unroll
    for (int o = 16; o > 0; o >>= 1) s += __shfl_xor_sync(0xffffffffu, s, o);
    if (lane == 0) invs[row] = 1.0f / fmaxf(sqrtf(s), 1e-12f);
}

// read x tile once -> nh,nl (straight) + xTh,xTl,nTh,nTl (transposed)
__global__ void k_prep(const float* __restrict__ x, const float* __restrict__ invs,
                       __half* __restrict__ nh, __half* __restrict__ nl,
                       __half* __restrict__ xTh, __half* __restrict__ xTl,
                       __half* __restrict__ nTh, __half* __restrict__ nTl) {
    __shared__ float tile[32][33];
    __shared__ float sinv[32];
    int c0 = blockIdx.x * 32, r0 = blockIdx.y * 32;
    if (threadIdx.y == 0) sinv[threadIdx.x] = invs[r0 + threadIdx.x];
    #pragma unroll
    for (int i = threadIdx.y; i < 32; i += 8)
        tile[i][threadIdx.x] = x[(size_t)(r0 + i) * DDIM + c0 + threadIdx.x];
    __syncthreads();
    // straight normalized split
    #pragma unroll
    for (int i = threadIdx.y; i < 32; i += 8) {
        float v = tile[i][threadIdx.x] * sinv[i];
        __half h = __float2half_rn(v);
        size_t o = (size_t)(r0 + i) * DDIM + c0 + threadIdx.x;
        nh[o] = h;
        nl[o] = __float2half_rn(v - __half2float(h));
    }
    // transposed splits (xT and nT)
    float is = sinv[threadIdx.x];
    #pragma unroll
    for (int i = threadIdx.y; i < 32; i += 8) {
        float v = tile[threadIdx.x][i];
        size_t o = (size_t)(c0 + i) * NROWS + r0 + threadIdx.x;
        __half xh = __float2half_rn(v);
        xTh[o] = xh;
        xTl[o] = __float2half_rn(v - __half2float(xh));
        float nv = v * is;
        __half nhh = __float2half_rn(nv);
        nTh[o] = nhh;
        nTl[o] = __float2half_rn(nv - __half2float(nhh));
    }
}

// transpose + split: src[R,C] fp32 -> dst[C,R] fp16 hi/lo  (used for W)
__global__ void k_tsplit(const float* __restrict__ src,
                         __half* __restrict__ dh, __half* __restrict__ dl,
                         int R, int C) {
    __shared__ float tile[32][33];
    int c0 = blockIdx.x * 32, r0 = blockIdx.y * 32;
    #pragma unroll
    for (int i = threadIdx.y; i < 32; i += 8)
        tile[i][threadIdx.x] = src[(size_t)(r0 + i) * C + c0 + threadIdx.x];
    __syncthreads();
    #pragma unroll
    for (int i = threadIdx.y; i < 32; i += 8) {
        float v = tile[threadIdx.x][i];
        __half h = __float2half_rn(v);
        size_t o = (size_t)(c0 + i) * R + r0 + threadIdx.x;
        dh[o] = h;
        dl[o] = __float2half_rn(v - __half2float(h));
    }
}

// reduce ZSPLIT partials + split, exploiting G symmetry (mirror lower from upper)
__global__ void k_reduce_split_sym(const float* __restrict__ p,
                                   __half* __restrict__ dh, __half* __restrict__ dl) {
    const int n = DDIM * DDIM;
    int c0 = blockIdx.x * 32, r0 = blockIdx.y * 32;
    if ((blockIdx.y >> 2) <= (blockIdx.x >> 2)) {
        #pragma unroll
        for (int i = threadIdx.y; i < 32; i += 8) {
            size_t o = (size_t)(r0 + i) * DDIM + c0 + threadIdx.x;
            float s = 0.0f;
            #pragma unroll
            for (int z = 0; z < ZSPLIT; z++) s += p[o + (size_t)z * n];
            __half h = __float2half_rn(s);
            dh[o] = h;
            dl[o] = __float2half_rn(s - __half2float(h));
        }
    } else {
        __shared__ float tile[32][33];
        #pragma unroll
        for (int i = threadIdx.y; i < 32; i += 8) {
            size_t o = (size_t)(c0 + i) * DDIM + r0 + threadIdx.x;
            float s = 0.0f;
            #pragma unroll
            for (int z = 0; z < ZSPLIT; z++) s += p[o + (size_t)z * n];
            tile[i][threadIdx.x] = s;
        }
        __syncthreads();
        #pragma unroll
        for (int i = threadIdx.y; i < 32; i += 8) {
            float v = tile[threadIdx.x][i];
            size_t o = (size_t)(r0 + i) * DDIM + c0 + threadIdx.x;
            __half h = __float2half_rn(v);
            dh[o] = h;
            dl[o] = __float2half_rn(v - __half2float(h));
        }
    }
}

// reduce ZSPLIT2 partials of M + TRANSPOSE + split -> MT hi/lo
__global__ void k_reduce_tsplit(const float* __restrict__ p,
                                __half* __restrict__ dh, __half* __restrict__ dl) {
    __shared__ float tile[32][33];
    const int n = DDIM * DDIM;
    int c0 = blockIdx.x * 32, r0 = blockIdx.y * 32;
    #pragma unroll
    for (int i = threadIdx.y; i < 32; i += 8) {
        size_t o = (size_t)(r0 + i) * DDIM + c0 + threadIdx.x;
        float s = 0.0f;
        #pragma unroll
        for (int z = 0; z < ZSPLIT2; z++) s += p[o + (size_t)z * n];
        tile[i][threadIdx.x] = s;
    }
    __syncthreads();
    #pragma unroll
    for (int i = threadIdx.y; i < 32; i += 8) {
        float v = tile[threadIdx.x][i];
        __half h = __float2half_rn(v);
        size_t o = (size_t)(c0 + i) * DDIM + r0 + threadIdx.x;
        dh[o] = h;
        dl[o] = __float2half_rn(v - __half2float(h));
    }
}

// ---------------- fp16x3 HMMA GEMM, 3-stage cp.async pipeline ----------------
// hi term: f32 acc; corrections (AlBh + AhBl): shared f16 acc (full-rate).
// symUpper != 0: skip blocks with row_blk > col_blk.
#define STAGE_BYTES 32768
#define NSTAGE 3

__global__ __launch_bounds__(256) void k_mma_gemm(
    const __half* __restrict__ Ah, const __half* __restrict__ Al,
    const __half* __restrict__ Bh, const __half* __restrict__ Bl,
    float* __restrict__ C, int ldk, int kPerZ, int ldc, int partStride, int symUpper)
{
    if (symUpper && blockIdx.y > blockIdx.x) return;

    extern __shared__ char smem[];
    uint32_t sbase = smem_u32(smem);
    int t = threadIdx.x;
    int lane = t & 31, w = t >> 5;
    int wm = w >> 2, wn = w & 3;                 // warp grid 2 x 4
    int i0 = blockIdx.y * 128, j0 = blockIdx.x * 128;
    int kbase = blockIdx.z * kPerZ;
    int T = kPerZ >> 5;                          // k-tiles of 32

    int g = lane >> 3, lr = lane & 7;
    int rA = wm * 64 + ((g & 1) << 3) + lr;
    uint32_t aRow = sbase + (uint32_t)rA * 128;
    uint32_t sA = (uint32_t)(rA & 7);
    uint32_t cAoff = (uint32_t)(g >> 1);
    int rB = wn * 32 + ((g >> 1) << 3) + lr;
    uint32_t bRow = sbase + 16384u + (uint32_t)rB * 128;
    uint32_t sB = (uint32_t)(rB & 7);
    uint32_t cBoff = (uint32_t)(g & 1);

    float acc[4][4][4];
    uint32_t corr[4][4][2];
    #pragma unroll
    for (int a = 0; a < 4; a++)
        #pragma unroll
        for (int b = 0; b < 4; b++) {
            #pragma unroll
            for (int c = 0; c < 4; c++) acc[a][b][c] = 0.0f;
            corr[a][b][0] = 0u; corr[a][b][1] = 0u;
        }

    auto load_stage = [&](int kt, int buf) {
        int kk = kbase + kt * 32;
        uint32_t dstBase = sbase + (uint32_t)buf * STAGE_BYTES;
        #pragma unroll
        for (int i = 0; i < 8; i++) {
            int e = t + i * 256;
            int tile = e >> 10;
            int idx = e & 1023;
            int r = idx >> 3, l = idx & 7;
            uint32_t phys = dstBase + (uint32_t)tile * 16384u + (uint32_t)r * 128u
                          + (uint32_t)(((l ^ (r & 7)) << 4));
            const __half* srcp;
            int kofs = (l & 3) * 8;
            if (tile == 0) {
                srcp = (l < 4) ? Ah : Al;
                srcp += (size_t)(i0 + r) * ldk + kk + kofs;
            } else {
                srcp = (l < 4) ? Bh : Bl;
                srcp += (size_t)(j0 + r) * ldk + kk + kofs;
            }
            cp16(phys, srcp);
        }
        CP_COMMIT();
    };

    load_stage(0, 0);
    load_stage(1, 1);

    int bufNext = 2;   // buffer index for stage kt+2 at iteration kt
    int bufCur = 0;    // buffer index for stage kt
    for (int kt = 0; kt < T; kt++) {
        if (kt + 2 < T) load_stage(kt + 2, bufNext); else CP_COMMIT();
        CP_WAIT2();
        __syncthreads();
        uint32_t stOff = (uint32_t)bufCur * STAGE_BYTES;

        #pragma unroll
        for (int ks = 0; ks < 2; ks++) {
            uint32_t aH[4][4], aL[4][4], bH[8], bL[8];
            uint32_t cbH = (uint32_t)(ks * 2);
            uint32_t cbL = cbH + 4;
            #pragma unroll
            for (int mt = 0; mt < 4; mt++) {
                uint32_t rowa = aRow + stOff + (uint32_t)(mt * 16) * 128u;
                ldsm4(aH[mt], rowa + (((cbH + cAoff) ^ sA) << 4));
                ldsm4(aL[mt], rowa + (((cbL + cAoff) ^ sA) << 4));
            }
            #pragma unroll
            for (int nt = 0; nt < 2; nt++) {
                uint32_t rowb = bRow + stOff + (uint32_t)(nt * 16) * 128u;
                ldsm4(&bH[nt * 4], rowb + (((cbH + cBoff) ^ sB) << 4));
                ldsm4(&bL[nt * 4], rowb + (((cbL + cBoff) ^ sB) << 4));
            }
            #pragma unroll
            for (int mt = 0; mt < 4; mt++) {
                #pragma unroll
                for (int j = 0; j < 4; j++) {
                    mma16816(acc[mt][j], aH[mt], &bH[j * 2]);
                    mma16816_f16(corr[mt][j], aL[mt], &bH[j * 2]);
                    mma16816_f16(corr[mt][j], aH[mt], &bL[j * 2]);
                }
            }
        }
        __syncthreads();
        bufCur = bufCur + 1 == NSTAGE ? 0 : bufCur + 1;
        bufNext = bufNext + 1 == NSTAGE ? 0 : bufNext + 1;
    }

    // ---- epilogue: merge f16 corrections into f32 accums ----
    float* Cz = C + (size_t)blockIdx.z * partStride;
    int qid = lane >> 2, tc = lane & 3;
    #pragma unroll
    for (int mt = 0; mt < 4; mt++) {
        int r0 = i0 + wm * 64 + mt * 16 + qid;
        #pragma unroll
        for (int j = 0; j < 4; j++) {
            __half2 p0 = *(__half2*)&corr[mt][j][0];   // elems 0,1
            __half2 p1 = *(__half2*)&corr[mt][j][1];   // elems 2,3
            int cc = j0 + wn * 32 + j * 8 + tc * 2;
            *(float2*)&Cz[(size_t)r0 * ldc + cc] =
                make_float2(acc[mt][j][0] + __half2float(p0.x),
                            acc[mt][j][1] + __half2float(p0.y));
            *(float2*)&Cz[(size_t)(r0 + 8) * ldc + cc] =
                make_float2(acc[mt][j][2] + __half2float(p1.x),
                            acc[mt][j][3] + __half2float(p1.y));
        }
    }
}

// ---------------- launch ----------------
extern "C" void kernel_launch(void* const* d_in, const int* in_sizes, int n_in,
                              void* d_out, int out_size)
{
    const float* x = (const float*)d_in[0];   // [n, d]
    const float* w = (const float*)d_in[1];   // [d, d]
    float* out = (float*)d_out;               // [n, d]

    int d = (int)(sqrt((double)in_sizes[1]) + 0.5);
    int n = in_sizes[0] / d;

    float *invs, *Gpart;
    __half *nh, *nl, *nTh, *nTl, *xTh, *xTl, *WTh, *WTl, *Gh, *Gl, *MTh, *MTl;
    cudaGetSymbolAddress((void**)&invs, g_invs);
    cudaGetSymbolAddress((void**)&nh, g_norm_h);   cudaGetSymbolAddress((void**)&nl, g_norm_l);
    cudaGetSymbolAddress((void**)&nTh, g_normT_h); cudaGetSymbolAddress((void**)&nTl, g_normT_l);
    cudaGetSymbolAddress((void**)&xTh, g_xT_h);    cudaGetSymbolAddress((void**)&xTl, g_xT_l);
    cudaGetSymbolAddress((void**)&WTh, g_WT_h);    cudaGetSymbolAddress((void**)&WTl, g_WT_l);
    cudaGetSymbolAddress((void**)&Gpart, g_Gpart);
    cudaGetSymbolAddress((void**)&Gh, g_G_h);      cudaGetSymbolAddress((void**)&Gl, g_G_l);
    cudaGetSymbolAddress((void**)&MTh, g_MT_h);    cudaGetSymbolAddress((void**)&MTl, g_MT_l);

    cudaFuncSetAttribute(k_mma_gemm, cudaFuncAttributeMaxDynamicSharedMemorySize,
                         NSTAGE * STAGE_BYTES);

    dim3 tb(32, 8);

    // idx 0: row norms
    k_rownorm<<<n / 8, 256>>>(x, invs);
    // idx 1: fused prep (nh,nl + xT,nT hi/lo)
    k_prep<<<dim3(d / 32, n / 32), tb>>>(x, invs, nh, nl, xTh, xTl, nTh, nTl);
    // idx 2: W transpose+split (needed only by GEMM2)
    k_tsplit<<<dim3(d / 32, d / 32), tb>>>(w, WTh, WTl, d, d);
    // idx 3: G = norm^T @ x (K=n, ZSPLIT partials) — upper-triangular blocks; PROFILED SLOT
    k_mma_gemm<<<dim3(d / 128, d / 128, ZSPLIT), 256, NSTAGE * STAGE_BYTES>>>(
        nTh, nTl, xTh, xTl, Gpart, n, n / ZSPLIT, d, d * d, 1);
    // idx 4: reduce G partials + mirror lower + split
    k_reduce_split_sym<<<dim3(d / 32, d / 32), tb>>>(Gpart, Gh, Gl);
    // idx 5: M partials = G @ W (K split by ZSPLIT2; reuse Gpart)
    k_mma_gemm<<<dim3(d / 128, d / 128, ZSPLIT2), 256, NSTAGE * STAGE_BYTES>>>(
        Gh, Gl, WTh, WTl, Gpart, d, d / ZSPLIT2, d, d * d, 0);
    // idx 6: reduce M partials + transpose + split
    k_reduce_tsplit<<<dim3(d / 32, d / 32), tb>>>(Gpart, MTh, MTl);
    // idx 7: out = norm @ M
    k_mma_gemm<<<dim3(d / 128, n / 128, 1), 256, NSTAGE * STAGE_BYTES>>>(
        nh, nl, MTh, MTl, out, d, d, d, 0, 0);
}

// round 11
// speedup vs baseline: 4.1774x; 1.2351x over previous
#include <cuda_runtime.h>
#include <cuda_fp16.h>
#include <math.h>
#include <stdint.h>

#define NROWS 8192
#define DDIM  1024
#define ZSPLIT 4     // GEMM1 k-split
#define ZSPLIT2 4    // GEMM2 k-split

// ---------------- scratch (device globals; no allocation) ----------------
__device__ float  g_invs  [NROWS];
__device__ __half g_norm_h[NROWS * DDIM];
__device__ __half g_norm_l[NROWS * DDIM];
__device__ __half g_normT_h[DDIM * NROWS];
__device__ __half g_normT_l[DDIM * NROWS];
__device__ __half g_xT_h  [DDIM * NROWS];
__device__ __half g_xT_l  [DDIM * NROWS];
__device__ __half g_WT_h  [DDIM * DDIM];
__device__ __half g_WT_l  [DDIM * DDIM];
__device__ float  g_Gpart [ZSPLIT * DDIM * DDIM];   // reused for M partials
__device__ __half g_G_h   [DDIM * DDIM];
__device__ __half g_G_l   [DDIM * DDIM];
__device__ __half g_MT_h  [DDIM * DDIM];
__device__ __half g_MT_l  [DDIM * DDIM];

// ---------------- PTX helpers ----------------
__device__ __forceinline__ uint32_t smem_u32(const void* p) {
    uint32_t a;
    asm("{ .reg .u64 t; cvta.to.shared.u64 t, %1; cvt.u32.u64 %0, t; }" : "=r"(a) : "l"(p));
    return a;
}
__device__ __forceinline__ void cp16(uint32_t dst, const void* src) {
    asm volatile("cp.async.cg.shared.global [%0], [%1], 16;" :: "r"(dst), "l"(src));
}
#define CP_COMMIT() asm volatile("cp.async.commit_group;" ::: "memory")
#define CP_WAIT1()  asm volatile("cp.async.wait_group 1;" ::: "memory")

__device__ __forceinline__ void ldsm4(uint32_t* r, uint32_t addr) {
    asm volatile("ldmatrix.sync.aligned.m8n8.x4.shared.b16 {%0,%1,%2,%3}, [%4];"
                 : "=r"(r[0]), "=r"(r[1]), "=r"(r[2]), "=r"(r[3]) : "r"(addr));
}
__device__ __forceinline__ void mma16816(float* c, const uint32_t* a, const uint32_t* b) {
    asm volatile(
        "mma.sync.aligned.m16n8k16.row.col.f32.f16.f16.f32 "
        "{%0,%1,%2,%3}, {%4,%5,%6,%7}, {%8,%9}, {%0,%1,%2,%3};"
        : "+f"(c[0]), "+f"(c[1]), "+f"(c[2]), "+f"(c[3])
        : "r"(a[0]), "r"(a[1]), "r"(a[2]), "r"(a[3]), "r"(b[0]), "r"(b[1]));
}
__device__ __forceinline__ void mma16816_f16(uint32_t* c, const uint32_t* a, const uint32_t* b) {
    asm volatile(
        "mma.sync.aligned.m16n8k16.row.col.f16.f16.f16.f16 "
        "{%0,%1}, {%2,%3,%4,%5}, {%6,%7}, {%0,%1};"
        : "+r"(c[0]), "+r"(c[1])
        : "r"(a[0]), "r"(a[1]), "r"(a[2]), "r"(a[3]), "r"(b[0]), "r"(b[1]));
}

// ---------------- prep kernels ----------------
__global__ void k_rownorm(const float* __restrict__ x, float* __restrict__ invs) {
    int wid = threadIdx.x >> 5, lane = threadIdx.x & 31;
    int row = blockIdx.x * 8 + wid;
    const float4* xr = (const float4*)(x + (size_t)row * DDIM);
    float s = 0.0f;
    #pragma unroll
    for (int j = 0; j < 8; j++) {
        float4 v = xr[lane + 32 * j];
        s += v.x * v.x + v.y * v.y + v.z * v.z + v.w * v.w;
    }
    #pragma unroll
    for (int o = 16; o > 0; o >>= 1) s += __shfl_xor_sync(0xffffffffu, s, o);
    if (lane == 0) invs[row] = 1.0f / fmaxf(sqrtf(s), 1e-12f);
}

__global__ void k_prep(const float* __restrict__ x, const float* __restrict__ invs,
                       __half* __restrict__ nh, __half* __restrict__ nl,
                       __half* __restrict__ xTh, __half* __restrict__ xTl,
                       __half* __restrict__ nTh, __half* __restrict__ nTl) {
    __shared__ float tile[32][33];
    __shared__ float sinv[32];
    int c0 = blockIdx.x * 32, r0 = blockIdx.y * 32;
    if (threadIdx.y == 0) sinv[threadIdx.x] = invs[r0 + threadIdx.x];
    #pragma unroll
    for (int i = threadIdx.y; i < 32; i += 8)
        tile[i][threadIdx.x] = x[(size_t)(r0 + i) * DDIM + c0 + threadIdx.x];
    __syncthreads();
    #pragma unroll
    for (int i = threadIdx.y; i < 32; i += 8) {
        float v = tile[i][threadIdx.x] * sinv[i];
        __half h = __float2half_rn(v);
        size_t o = (size_t)(r0 + i) * DDIM + c0 + threadIdx.x;
        nh[o] = h;
        nl[o] = __float2half_rn(v - __half2float(h));
    }
    float is = sinv[threadIdx.x];
    #pragma unroll
    for (int i = threadIdx.y; i < 32; i += 8) {
        float v = tile[threadIdx.x][i];
        size_t o = (size_t)(c0 + i) * NROWS + r0 + threadIdx.x;
        __half xh = __float2half_rn(v);
        xTh[o] = xh;
        xTl[o] = __float2half_rn(v - __half2float(xh));
        float nv = v * is;
        __half nhh = __float2half_rn(nv);
        nTh[o] = nhh;
        nTl[o] = __float2half_rn(nv - __half2float(nhh));
    }
}

__global__ void k_tsplit(const float* __restrict__ src,
                         __half* __restrict__ dh, __half* __restrict__ dl,
                         int R, int C) {
    __shared__ float tile[32][33];
    int c0 = blockIdx.x * 32, r0 = blockIdx.y * 32;
    #pragma unroll
    for (int i = threadIdx.y; i < 32; i += 8)
        tile[i][threadIdx.x] = src[(size_t)(r0 + i) * C + c0 + threadIdx.x];
    __syncthreads();
    #pragma unroll
    for (int i = threadIdx.y; i < 32; i += 8) {
        float v = tile[threadIdx.x][i];
        __half h = __float2half_rn(v);
        size_t o = (size_t)(c0 + i) * R + r0 + threadIdx.x;
        dh[o] = h;
        dl[o] = __float2half_rn(v - __half2float(h));
    }
}

// reduce ZSPLIT partials + split, mirror lower from upper (G symmetric)
__global__ void k_reduce_split_sym(const float* __restrict__ p,
                                   __half* __restrict__ dh, __half* __restrict__ dl) {
    const int n = DDIM * DDIM;
    int c0 = blockIdx.x * 32, r0 = blockIdx.y * 32;
    if ((blockIdx.y >> 2) <= (blockIdx.x >> 2)) {
        #pragma unroll
        for (int i = threadIdx.y; i < 32; i += 8) {
            size_t o = (size_t)(r0 + i) * DDIM + c0 + threadIdx.x;
            float s = 0.0f;
            #pragma unroll
            for (int z = 0; z < ZSPLIT; z++) s += p[o + (size_t)z * n];
            __half h = __float2half_rn(s);
            dh[o] = h;
            dl[o] = __float2half_rn(s - __half2float(h));
        }
    } else {
        __shared__ float tile[32][33];
        #pragma unroll
        for (int i = threadIdx.y; i < 32; i += 8) {
            size_t o = (size_t)(c0 + i) * DDIM + r0 + threadIdx.x;
            float s = 0.0f;
            #pragma unroll
            for (int z = 0; z < ZSPLIT; z++) s += p[o + (size_t)z * n];
            tile[i][threadIdx.x] = s;
        }
        __syncthreads();
        #pragma unroll
        for (int i = threadIdx.y; i < 32; i += 8) {
            float v = tile[threadIdx.x][i];
            size_t o = (size_t)(r0 + i) * DDIM + c0 + threadIdx.x;
            __half h = __float2half_rn(v);
            dh[o] = h;
            dl[o] = __float2half_rn(v - __half2float(h));
        }
    }
}

// reduce ZSPLIT2 partials of M + transpose + split -> MT hi/lo
__global__ void k_reduce_tsplit(const float* __restrict__ p,
                                __half* __restrict__ dh, __half* __restrict__ dl) {
    __shared__ float tile[32][33];
    const int n = DDIM * DDIM;
    int c0 = blockIdx.x * 32, r0 = blockIdx.y * 32;
    #pragma unroll
    for (int i = threadIdx.y; i < 32; i += 8) {
        size_t o = (size_t)(r0 + i) * DDIM + c0 + threadIdx.x;
        float s = 0.0f;
        #pragma unroll
        for (int z = 0; z < ZSPLIT2; z++) s += p[o + (size_t)z * n];
        tile[i][threadIdx.x] = s;
    }
    __syncthreads();
    #pragma unroll
    for (int i = threadIdx.y; i < 32; i += 8) {
        float v = tile[threadIdx.x][i];
        __half h = __float2half_rn(v);
        size_t o = (size_t)(c0 + i) * DDIM + r0 + threadIdx.x;
        dh[o] = h;
        dl[o] = __float2half_rn(v - __half2float(h));
    }
}

// ---------------- fp16x3 HMMA GEMM ----------------
// BK=64 stages (3 buffers, 64KB each), single barrier per stage,
// register double-buffered fragments across the 4 ks sub-steps.
// triMap != 0: blockIdx.x is linear upper-tri pair index -> (i,j), i<=j (8x8 grid).
#define STAGE_BYTES 65536
#define NSTAGE 3

__global__ __launch_bounds__(256, 1) void k_mma_gemm(
    const __half* __restrict__ Ah, const __half* __restrict__ Al,
    const __half* __restrict__ Bh, const __half* __restrict__ Bl,
    float* __restrict__ C, int ldk, int kPerZ, int ldc, int partStride, int triMap)
{
    int bi, bj;
    if (triMap) {
        // exact integer map: p in [0,36) -> (i,j), i<=j<8; row i has 8-i entries
        int p = blockIdx.x;
        int i = 0, rem = p;
        #pragma unroll
        for (int r = 0; r < 8; r++) {
            int len = 8 - r;
            if (rem >= len && i == r) { rem -= len; i = r + 1; }
        }
        bi = i; bj = i + rem;
    } else {
        bi = blockIdx.y; bj = blockIdx.x;
    }

    extern __shared__ char smem[];
    uint32_t sbase = smem_u32(smem);
    int t = threadIdx.x;
    int lane = t & 31, w = t >> 5;
    int wm = w >> 2, wn = w & 3;                 // warp grid 2 x 4
    int i0 = bi * 128, j0 = bj * 128;
    int kbase = blockIdx.z * kPerZ;
    int T = kPerZ >> 6;                          // k-tiles of 64

    int g = lane >> 3, lr = lane & 7;
    int rA = wm * 64 + ((g & 1) << 3) + lr;
    uint32_t aRow = sbase + (uint32_t)rA * 128;
    uint32_t sA = (uint32_t)(rA & 7);
    uint32_t cAoff = (uint32_t)(g >> 1);
    int rB = wn * 32 + ((g >> 1) << 3) + lr;
    uint32_t bRow = sbase + 16384u + (uint32_t)rB * 128;
    uint32_t sB = (uint32_t)(rB & 7);
    uint32_t cBoff = (uint32_t)(g & 1);

    float acc[4][4][4];
    uint32_t corr[4][4][2];
    #pragma unroll
    for (int a = 0; a < 4; a++)
        #pragma unroll
        for (int b = 0; b < 4; b++) {
            #pragma unroll
            for (int c = 0; c < 4; c++) acc[a][b][c] = 0.0f;
            corr[a][b][0] = 0u; corr[a][b][1] = 0u;
        }

    // fragment double buffers
    uint32_t aH[2][4][4], aL[2][4][4], bH[2][8], bL[2][8];

    auto load_stage = [&](int kt, int buf) {
        int kk = kbase + kt * 64;
        uint32_t dstBase = sbase + (uint32_t)buf * STAGE_BYTES;
        #pragma unroll
        for (int i = 0; i < 16; i++) {
            int e = t + i * 256;                 // 0..4095
            int sub = e >> 11;                   // k-half: 0 => k[0:32), 1 => k[32:64)
            int rem = e & 2047;
            int tile = rem >> 10;                // 0=A, 1=B
            int idx = rem & 1023;
            int r = idx >> 3, l = idx & 7;
            uint32_t phys = dstBase + ((uint32_t)sub << 15) + ((uint32_t)tile << 14)
                          + (uint32_t)r * 128u + (uint32_t)(((l ^ (r & 7)) << 4));
            int kofs = kk + sub * 32 + (l & 3) * 8;
            const __half* srcp;
            if (tile == 0) {
                srcp = ((l & 7) < 4 ? Ah : Al) + (size_t)(i0 + r) * ldk + kofs;
            } else {
                srcp = ((l & 7) < 4 ? Bh : Bl) + (size_t)(j0 + r) * ldk + kofs;
            }
            cp16(phys, srcp);
        }
        CP_COMMIT();
    };

    auto load_frags = [&](int ks, int fb, uint32_t stOff) {
        uint32_t so = stOff + ((uint32_t)(ks >> 1) << 15);
        uint32_t cbH = (uint32_t)((ks & 1) * 2);
        uint32_t cbL = cbH + 4;
        #pragma unroll
        for (int mt = 0; mt < 4; mt++) {
            uint32_t rowa = aRow + so + (uint32_t)(mt * 16) * 128u;
            ldsm4(aH[fb][mt], rowa + (((cbH + cAoff) ^ sA) << 4));
            ldsm4(aL[fb][mt], rowa + (((cbL + cAoff) ^ sA) << 4));
        }
        #pragma unroll
        for (int nt = 0; nt < 2; nt++) {
            uint32_t rowb = bRow + so + (uint32_t)(nt * 16) * 128u;
            ldsm4(&bH[fb][nt * 4], rowb + (((cbH + cBoff) ^ sB) << 4));
            ldsm4(&bL[fb][nt * 4], rowb + (((cbL + cBoff) ^ sB) << 4));
        }
    };

    load_stage(0, 0);

    int bufCur = 0;
    for (int kt = 0; kt < T; kt++) {
        if (kt + 1 < T) load_stage(kt + 1, bufCur + 1 == NSTAGE ? 0 : bufCur + 1);
        else CP_COMMIT();
        CP_WAIT1();
        __syncthreads();
        uint32_t stOff = (uint32_t)bufCur * STAGE_BYTES;

        load_frags(0, 0, stOff);
        #pragma unroll
        for (int ks = 0; ks < 4; ks++) {
            int cur = ks & 1;
            if (ks < 3) load_frags(ks + 1, cur ^ 1, stOff);
            #pragma unroll
            for (int mt = 0; mt < 4; mt++) {
                #pragma unroll
                for (int j = 0; j < 4; j++) {
                    mma16816(acc[mt][j], aH[cur][mt], &bH[cur][j * 2]);
                    mma16816_f16(corr[mt][j], aL[cur][mt], &bH[cur][j * 2]);
                    mma16816_f16(corr[mt][j], aH[cur][mt], &bL[cur][j * 2]);
                }
            }
        }
        bufCur = bufCur + 1 == NSTAGE ? 0 : bufCur + 1;
    }

    // ---- epilogue: merge f16 corrections into f32 accums ----
    float* Cz = C + (size_t)blockIdx.z * partStride;
    int qid = lane >> 2, tc = lane & 3;
    #pragma unroll
    for (int mt = 0; mt < 4; mt++) {
        int r0 = i0 + wm * 64 + mt * 16 + qid;
        #pragma unroll
        for (int j = 0; j < 4; j++) {
            __half2 p0 = *(__half2*)&corr[mt][j][0];
            __half2 p1 = *(__half2*)&corr[mt][j][1];
            int cc = j0 + wn * 32 + j * 8 + tc * 2;
            *(float2*)&Cz[(size_t)r0 * ldc + cc] =
                make_float2(acc[mt][j][0] + __half2float(p0.x),
                            acc[mt][j][1] + __half2float(p0.y));
            *(float2*)&Cz[(size_t)(r0 + 8) * ldc + cc] =
                make_float2(acc[mt][j][2] + __half2float(p1.x),
                            acc[mt][j][3] + __half2float(p1.y));
        }
    }
}

// ---------------- launch ----------------
extern "C" void kernel_launch(void* const* d_in, const int* in_sizes, int n_in,
                              void* d_out, int out_size)
{
    const float* x = (const float*)d_in[0];   // [n, d]
    const float* w = (const float*)d_in[1];   // [d, d]
    float* out = (float*)d_out;               // [n, d]

    int d = (int)(sqrt((double)in_sizes[1]) + 0.5);
    int n = in_sizes[0] / d;

    float *invs, *Gpart;
    __half *nh, *nl, *nTh, *nTl, *xTh, *xTl, *WTh, *WTl, *Gh, *Gl, *MTh, *MTl;
    cudaGetSymbolAddress((void**)&invs, g_invs);
    cudaGetSymbolAddress((void**)&nh, g_norm_h);   cudaGetSymbolAddress((void**)&nl, g_norm_l);
    cudaGetSymbolAddress((void**)&nTh, g_normT_h); cudaGetSymbolAddress((void**)&nTl, g_normT_l);
    cudaGetSymbolAddress((void**)&xTh, g_xT_h);    cudaGetSymbolAddress((void**)&xTl, g_xT_l);
    cudaGetSymbolAddress((void**)&WTh, g_WT_h);    cudaGetSymbolAddress((void**)&WTl, g_WT_l);
    cudaGetSymbolAddress((void**)&Gpart, g_Gpart);
    cudaGetSymbolAddress((void**)&Gh, g_G_h);      cudaGetSymbolAddress((void**)&Gl, g_G_l);
    cudaGetSymbolAddress((void**)&MTh, g_MT_h);    cudaGetSymbolAddress((void**)&MTl, g_MT_l);

    cudaFuncSetAttribute(k_mma_gemm, cudaFuncAttributeMaxDynamicSharedMemorySize,
                         NSTAGE * STAGE_BYTES);

    dim3 tb(32, 8);

    // idx 0: row norms
    k_rownorm<<<n / 8, 256>>>(x, invs);
    // idx 1: fused prep
    k_prep<<<dim3(d / 32, n / 32), tb>>>(x, invs, nh, nl, xTh, xTl, nTh, nTl);
    // idx 2: W transpose+split
    k_tsplit<<<dim3(d / 32, d / 32), tb>>>(w, WTh, WTl, d, d);
    // idx 3: G = norm^T @ x — compact upper-tri grid (36 pairs), ZSPLIT k-split; PROFILED
    k_mma_gemm<<<dim3(36, 1, ZSPLIT), 256, NSTAGE * STAGE_BYTES>>>(
        nTh, nTl, xTh, xTl, Gpart, n, n / ZSPLIT, d, d * d, 1);
    // idx 4: reduce G partials + mirror lower + split
    k_reduce_split_sym<<<dim3(d / 32, d / 32), tb>>>(Gpart, Gh, Gl);
    // idx 5: M partials = G @ W (K split by ZSPLIT2; reuse Gpart)
    k_mma_gemm<<<dim3(d / 128, d / 128, ZSPLIT2), 256, NSTAGE * STAGE_BYTES>>>(
        Gh, Gl, WTh, WTl, Gpart, d, d / ZSPLIT2, d, d * d, 0);
    // idx 6: reduce M partials + transpose + split
    k_reduce_tsplit<<<dim3(d / 32, d / 32), tb>>>(Gpart, MTh, MTl);
    // idx 7: out = norm @ M
    k_mma_gemm<<<dim3(d / 128, n / 128, 1), 256, NSTAGE * STAGE_BYTES>>>(
        nh, nl, MTh, MTl, out, d, d, d, 0, 0);
}

// round 12
// speedup vs baseline: 4.2256x; 1.0115x over previous
#include <cuda_runtime.h>
#include <cuda_fp16.h>
#include <math.h>
#include <stdint.h>

#define NROWS 8192
#define DDIM  1024
#define ZSPLIT 4     // GEMM1 k-split
#define ZSPLIT2 2    // GEMM2 k-split

// ---------------- scratch (device globals; no allocation) ----------------
__device__ float  g_invs  [NROWS];
__device__ __half g_norm_h[NROWS * DDIM];
__device__ __half g_normT_h[DDIM * NROWS];
__device__ __half g_normT_l[DDIM * NROWS];
__device__ __half g_xT_h  [DDIM * NROWS];
__device__ __half g_xT_l  [DDIM * NROWS];
__device__ __half g_WT_h  [DDIM * DDIM];
__device__ __half g_WT_l  [DDIM * DDIM];
__device__ float  g_Gpart [ZSPLIT * DDIM * DDIM];   // reused for M partials
__device__ __half g_G_h   [DDIM * DDIM];
__device__ __half g_G_l   [DDIM * DDIM];
__device__ __half g_MT_h  [DDIM * DDIM];
__device__ __half g_MT_l  [DDIM * DDIM];

// ---------------- PTX helpers ----------------
__device__ __forceinline__ uint32_t smem_u32(const void* p) {
    uint32_t a;
    asm("{ .reg .u64 t; cvta.to.shared.u64 t, %1; cvt.u32.u64 %0, t; }" : "=r"(a) : "l"(p));
    return a;
}
__device__ __forceinline__ void cp16(uint32_t dst, const void* src) {
    asm volatile("cp.async.cg.shared.global [%0], [%1], 16;" :: "r"(dst), "l"(src));
}
#define CP_COMMIT() asm volatile("cp.async.commit_group;" ::: "memory")
#define CP_WAIT1()  asm volatile("cp.async.wait_group 1;" ::: "memory")

__device__ __forceinline__ void ldsm4(uint32_t* r, uint32_t addr) {
    asm volatile("ldmatrix.sync.aligned.m8n8.x4.shared.b16 {%0,%1,%2,%3}, [%4];"
                 : "=r"(r[0]), "=r"(r[1]), "=r"(r[2]), "=r"(r[3]) : "r"(addr));
}
__device__ __forceinline__ void mma16816(float* c, const uint32_t* a, const uint32_t* b) {
    asm volatile(
        "mma.sync.aligned.m16n8k16.row.col.f32.f16.f16.f32 "
        "{%0,%1,%2,%3}, {%4,%5,%6,%7}, {%8,%9}, {%0,%1,%2,%3};"
        : "+f"(c[0]), "+f"(c[1]), "+f"(c[2]), "+f"(c[3])
        : "r"(a[0]), "r"(a[1]), "r"(a[2]), "r"(a[3]), "r"(b[0]), "r"(b[1]));
}
__device__ __forceinline__ void mma16816_f16(uint32_t* c, const uint32_t* a, const uint32_t* b) {
    asm volatile(
        "mma.sync.aligned.m16n8k16.row.col.f16.f16.f16.f16 "
        "{%0,%1}, {%2,%3,%4,%5}, {%6,%7}, {%0,%1};"
        : "+r"(c[0]), "+r"(c[1])
        : "r"(a[0]), "r"(a[1]), "r"(a[2]), "r"(a[3]), "r"(b[0]), "r"(b[1]));
}

// ---------------- prep kernels ----------------
__global__ void k_rownorm(const float* __restrict__ x, float* __restrict__ invs) {
    int wid = threadIdx.x >> 5, lane = threadIdx.x & 31;
    int row = blockIdx.x * 8 + wid;
    const float4* xr = (const float4*)(x + (size_t)row * DDIM);
    float s = 0.0f;
    #pragma unroll
    for (int j = 0; j < 8; j++) {
        float4 v = xr[lane + 32 * j];
        s += v.x * v.x + v.y * v.y + v.z * v.z + v.w * v.w;
    }
    #pragma unroll
    for (int o = 16; o > 0; o >>= 1) s += __shfl_xor_sync(0xffffffffu, s, o);
    if (lane == 0) invs[row] = 1.0f / fmaxf(sqrtf(s), 1e-12f);
}

// x tile -> nh (straight, hi only) + xT hi/lo + nT hi/lo (transposed)
__global__ void k_prep(const float* __restrict__ x, const float* __restrict__ invs,
                       __half* __restrict__ nh,
                       __half* __restrict__ xTh, __half* __restrict__ xTl,
                       __half* __restrict__ nTh, __half* __restrict__ nTl) {
    __shared__ float tile[32][33];
    __shared__ float sinv[32];
    int c0 = blockIdx.x * 32, r0 = blockIdx.y * 32;
    if (threadIdx.y == 0) sinv[threadIdx.x] = invs[r0 + threadIdx.x];
    #pragma unroll
    for (int i = threadIdx.y; i < 32; i += 8)
        tile[i][threadIdx.x] = x[(size_t)(r0 + i) * DDIM + c0 + threadIdx.x];
    __syncthreads();
    #pragma unroll
    for (int i = threadIdx.y; i < 32; i += 8) {
        float v = tile[i][threadIdx.x] * sinv[i];
        nh[(size_t)(r0 + i) * DDIM + c0 + threadIdx.x] = __float2half_rn(v);
    }
    float is = sinv[threadIdx.x];
    #pragma unroll
    for (int i = threadIdx.y; i < 32; i += 8) {
        float v = tile[threadIdx.x][i];
        size_t o = (size_t)(c0 + i) * NROWS + r0 + threadIdx.x;
        __half xh = __float2half_rn(v);
        xTh[o] = xh;
        xTl[o] = __float2half_rn(v - __half2float(xh));
        float nv = v * is;
        __half nhh = __float2half_rn(nv);
        nTh[o] = nhh;
        nTl[o] = __float2half_rn(nv - __half2float(nhh));
    }
}

__global__ void k_tsplit(const float* __restrict__ src,
                         __half* __restrict__ dh, __half* __restrict__ dl,
                         int R, int C) {
    __shared__ float tile[32][33];
    int c0 = blockIdx.x * 32, r0 = blockIdx.y * 32;
    #pragma unroll
    for (int i = threadIdx.y; i < 32; i += 8)
        tile[i][threadIdx.x] = src[(size_t)(r0 + i) * C + c0 + threadIdx.x];
    __syncthreads();
    #pragma unroll
    for (int i = threadIdx.y; i < 32; i += 8) {
        float v = tile[threadIdx.x][i];
        __half h = __float2half_rn(v);
        size_t o = (size_t)(c0 + i) * R + r0 + threadIdx.x;
        dh[o] = h;
        dl[o] = __float2half_rn(v - __half2float(h));
    }
}

// reduce ZSPLIT partials + split, mirror lower from upper (G symmetric)
__global__ void k_reduce_split_sym(const float* __restrict__ p,
                                   __half* __restrict__ dh, __half* __restrict__ dl) {
    const int n = DDIM * DDIM;
    int c0 = blockIdx.x * 32, r0 = blockIdx.y * 32;
    if ((blockIdx.y >> 2) <= (blockIdx.x >> 2)) {
        #pragma unroll
        for (int i = threadIdx.y; i < 32; i += 8) {
            size_t o = (size_t)(r0 + i) * DDIM + c0 + threadIdx.x;
            float s = 0.0f;
            #pragma unroll
            for (int z = 0; z < ZSPLIT; z++) s += p[o + (size_t)z * n];
            __half h = __float2half_rn(s);
            dh[o] = h;
            dl[o] = __float2half_rn(s - __half2float(h));
        }
    } else {
        __shared__ float tile[32][33];
        #pragma unroll
        for (int i = threadIdx.y; i < 32; i += 8) {
            size_t o = (size_t)(c0 + i) * DDIM + r0 + threadIdx.x;
            float s = 0.0f;
            #pragma unroll
            for (int z = 0; z < ZSPLIT; z++) s += p[o + (size_t)z * n];
            tile[i][threadIdx.x] = s;
        }
        __syncthreads();
        #pragma unroll
        for (int i = threadIdx.y; i < 32; i += 8) {
            float v = tile[threadIdx.x][i];
            size_t o = (size_t)(r0 + i) * DDIM + c0 + threadIdx.x;
            __half h = __float2half_rn(v);
            dh[o] = h;
            dl[o] = __float2half_rn(v - __half2float(h));
        }
    }
}

// reduce ZSPLIT2 partials of M + transpose + split -> MT hi/lo
__global__ void k_reduce_tsplit(const float* __restrict__ p,
                                __half* __restrict__ dh, __half* __restrict__ dl) {
    __shared__ float tile[32][33];
    const int n = DDIM * DDIM;
    int c0 = blockIdx.x * 32, r0 = blockIdx.y * 32;
    #pragma unroll
    for (int i = threadIdx.y; i < 32; i += 8) {
        size_t o = (size_t)(r0 + i) * DDIM + c0 + threadIdx.x;
        float s = 0.0f;
        #pragma unroll
        for (int z = 0; z < ZSPLIT2; z++) s += p[o + (size_t)z * n];
        tile[i][threadIdx.x] = s;
    }
    __syncthreads();
    #pragma unroll
    for (int i = threadIdx.y; i < 32; i += 8) {
        float v = tile[threadIdx.x][i];
        __half h = __float2half_rn(v);
        size_t o = (size_t)(c0 + i) * DDIM + r0 + threadIdx.x;
        dh[o] = h;
        dl[o] = __float2half_rn(v - __half2float(h));
    }
}

// ---------------- fp16 HMMA GEMM ----------------
// BK=64 stages (3 buffers, 64KB), single barrier/stage, reg double-buffered frags.
// useAl: include AlBh correction (A lo present). B lo always used.
// triMap != 0: blockIdx.x is linear upper-tri pair index -> (i,j), i<=j (8x8 grid).
#define STAGE_BYTES 65536
#define NSTAGE 3

__global__ __launch_bounds__(256, 1) void k_mma_gemm(
    const __half* __restrict__ Ah, const __half* __restrict__ Al,
    const __half* __restrict__ Bh, const __half* __restrict__ Bl,
    float* __restrict__ C, int ldk, int kPerZ, int ldc, int partStride,
    int triMap, int useAl)
{
    int bi, bj;
    if (triMap) {
        int p = blockIdx.x;
        int i = 0, rem = p;
        #pragma unroll
        for (int r = 0; r < 8; r++) {
            int len = 8 - r;
            if (rem >= len && i == r) { rem -= len; i = r + 1; }
        }
        bi = i; bj = i + rem;
    } else {
        bi = blockIdx.y; bj = blockIdx.x;
    }

    extern __shared__ char smem[];
    uint32_t sbase = smem_u32(smem);
    int t = threadIdx.x;
    int lane = t & 31, w = t >> 5;
    int wm = w >> 2, wn = w & 3;                 // warp grid 2 x 4
    int i0 = bi * 128, j0 = bj * 128;
    int kbase = blockIdx.z * kPerZ;
    int T = kPerZ >> 6;                          // k-tiles of 64

    int g = lane >> 3, lr = lane & 7;
    int rA = wm * 64 + ((g & 1) << 3) + lr;
    uint32_t aRow = sbase + (uint32_t)rA * 128;
    uint32_t sA = (uint32_t)(rA & 7);
    uint32_t cAoff = (uint32_t)(g >> 1);
    int rB = wn * 32 + ((g >> 1) << 3) + lr;
    uint32_t bRow = sbase + 16384u + (uint32_t)rB * 128;
    uint32_t sB = (uint32_t)(rB & 7);
    uint32_t cBoff = (uint32_t)(g & 1);

    float acc[4][4][4];
    uint32_t corr[4][4][2];
    #pragma unroll
    for (int a = 0; a < 4; a++)
        #pragma unroll
        for (int b = 0; b < 4; b++) {
            #pragma unroll
            for (int c = 0; c < 4; c++) acc[a][b][c] = 0.0f;
            corr[a][b][0] = 0u; corr[a][b][1] = 0u;
        }

    // fragment double buffers
    uint32_t aH[2][4][4], aL[2][4][4], bH[2][8], bL[2][8];

    auto load_stage = [&](int kt, int buf) {
        int kk = kbase + kt * 64;
        uint32_t dstBase = sbase + (uint32_t)buf * STAGE_BYTES;
        #pragma unroll
        for (int i = 0; i < 16; i++) {
            int e = t + i * 256;                 // 0..4095
            int sub = e >> 11;                   // k-half
            int rem = e & 2047;
            int tile = rem >> 10;                // 0=A, 1=B
            int idx = rem & 1023;
            int r = idx >> 3, l = idx & 7;
            if (!useAl && tile == 0 && l >= 4) continue;   // skip A-lo chunks
            uint32_t phys = dstBase + ((uint32_t)sub << 15) + ((uint32_t)tile << 14)
                          + (uint32_t)r * 128u + (uint32_t)(((l ^ (r & 7)) << 4));
            int kofs = kk + sub * 32 + (l & 3) * 8;
            const __half* srcp;
            if (tile == 0) {
                srcp = (l < 4 ? Ah : Al) + (size_t)(i0 + r) * ldk + kofs;
            } else {
                srcp = (l < 4 ? Bh : Bl) + (size_t)(j0 + r) * ldk + kofs;
            }
            cp16(phys, srcp);
        }
        CP_COMMIT();
    };

    auto load_frags = [&](int ks, int fb, uint32_t stOff) {
        uint32_t so = stOff + ((uint32_t)(ks >> 1) << 15);
        uint32_t cbH = (uint32_t)((ks & 1) * 2);
        uint32_t cbL = cbH + 4;
        #pragma unroll
        for (int mt = 0; mt < 4; mt++) {
            uint32_t rowa = aRow + so + (uint32_t)(mt * 16) * 128u;
            ldsm4(aH[fb][mt], rowa + (((cbH + cAoff) ^ sA) << 4));
            if (useAl) ldsm4(aL[fb][mt], rowa + (((cbL + cAoff) ^ sA) << 4));
        }
        #pragma unroll
        for (int nt = 0; nt < 2; nt++) {
            uint32_t rowb = bRow + so + (uint32_t)(nt * 16) * 128u;
            ldsm4(&bH[fb][nt * 4], rowb + (((cbH + cBoff) ^ sB) << 4));
            ldsm4(&bL[fb][nt * 4], rowb + (((cbL + cBoff) ^ sB) << 4));
        }
    };

    load_stage(0, 0);

    int bufCur = 0;
    for (int kt = 0; kt < T; kt++) {
        if (kt + 1 < T) load_stage(kt + 1, bufCur + 1 == NSTAGE ? 0 : bufCur + 1);
        else CP_COMMIT();
        CP_WAIT1();
        __syncthreads();
        uint32_t stOff = (uint32_t)bufCur * STAGE_BYTES;

        load_frags(0, 0, stOff);
        #pragma unroll
        for (int ks = 0; ks < 4; ks++) {
            int cur = ks & 1;
            if (ks < 3) load_frags(ks + 1, cur ^ 1, stOff);
            #pragma unroll
            for (int mt = 0; mt < 4; mt++) {
                #pragma unroll
                for (int j = 0; j < 4; j++) {
                    mma16816(acc[mt][j], aH[cur][mt], &bH[cur][j * 2]);
                    if (useAl) mma16816_f16(corr[mt][j], aL[cur][mt], &bH[cur][j * 2]);
                    mma16816_f16(corr[mt][j], aH[cur][mt], &bL[cur][j * 2]);
                }
            }
        }
        bufCur = bufCur + 1 == NSTAGE ? 0 : bufCur + 1;
    }

    // ---- epilogue: merge f16 corrections into f32 accums ----
    float* Cz = C + (size_t)blockIdx.z * partStride;
    int qid = lane >> 2, tc = lane & 3;
    #pragma unroll
    for (int mt = 0; mt < 4; mt++) {
        int r0 = i0 + wm * 64 + mt * 16 + qid;
        #pragma unroll
        for (int j = 0; j < 4; j++) {
            __half2 p0 = *(__half2*)&corr[mt][j][0];
            __half2 p1 = *(__half2*)&corr[mt][j][1];
            int cc = j0 + wn * 32 + j * 8 + tc * 2;
            *(float2*)&Cz[(size_t)r0 * ldc + cc] =
                make_float2(acc[mt][j][0] + __half2float(p0.x),
                            acc[mt][j][1] + __half2float(p0.y));
            *(float2*)&Cz[(size_t)(r0 + 8) * ldc + cc] =
                make_float2(acc[mt][j][2] + __half2float(p1.x),
                            acc[mt][j][3] + __half2float(p1.y));
        }
    }
}

// ---------------- launch ----------------
extern "C" void kernel_launch(void* const* d_in, const int* in_sizes, int n_in,
                              void* d_out, int out_size)
{
    const float* x = (const float*)d_in[0];   // [n, d]
    const float* w = (const float*)d_in[1];   // [d, d]
    float* out = (float*)d_out;               // [n, d]

    int d = (int)(sqrt((double)in_sizes[1]) + 0.5);
    int n = in_sizes[0] / d;

    float *invs, *Gpart;
    __half *nh, *nTh, *nTl, *xTh, *xTl, *WTh, *WTl, *Gh, *Gl, *MTh, *MTl;
    cudaGetSymbolAddress((void**)&invs, g_invs);
    cudaGetSymbolAddress((void**)&nh, g_norm_h);
    cudaGetSymbolAddress((void**)&nTh, g_normT_h); cudaGetSymbolAddress((void**)&nTl, g_normT_l);
    cudaGetSymbolAddress((void**)&xTh, g_xT_h);    cudaGetSymbolAddress((void**)&xTl, g_xT_l);
    cudaGetSymbolAddress((void**)&WTh, g_WT_h);    cudaGetSymbolAddress((void**)&WTl, g_WT_l);
    cudaGetSymbolAddress((void**)&Gpart, g_Gpart);
    cudaGetSymbolAddress((void**)&Gh, g_G_h);      cudaGetSymbolAddress((void**)&Gl, g_G_l);
    cudaGetSymbolAddress((void**)&MTh, g_MT_h);    cudaGetSymbolAddress((void**)&MTl, g_MT_l);

    cudaFuncSetAttribute(k_mma_gemm, cudaFuncAttributeMaxDynamicSharedMemorySize,
                         NSTAGE * STAGE_BYTES);

    dim3 tb(32, 8);

    // idx 0: row norms
    k_rownorm<<<n / 8, 256>>>(x, invs);
    // idx 1: fused prep (nh + xT,nT hi/lo)
    k_prep<<<dim3(d / 32, n / 32), tb>>>(x, invs, nh, xTh, xTl, nTh, nTl);
    // idx 2: W transpose+split
    k_tsplit<<<dim3(d / 32, d / 32), tb>>>(w, WTh, WTl, d, d);
    // idx 3: G = norm^T @ x — compact upper-tri grid (36 pairs), ZSPLIT k-split; PROFILED
    k_mma_gemm<<<dim3(36, 1, ZSPLIT), 256, NSTAGE * STAGE_BYTES>>>(
        nTh, nTl, xTh, xTl, Gpart, n, n / ZSPLIT, d, d * d, 1, 1);
    // idx 4: reduce G partials + mirror lower + split
    k_reduce_split_sym<<<dim3(d / 32, d / 32), tb>>>(Gpart, Gh, Gl);
    // idx 5: M partials = G @ W (K split by ZSPLIT2; reuse Gpart)
    k_mma_gemm<<<dim3(d / 128, d / 128, ZSPLIT2), 256, NSTAGE * STAGE_BYTES>>>(
        Gh, Gl, WTh, WTl, Gpart, d, d / ZSPLIT2, d, d * d, 0, 1);
    // idx 6: reduce M partials + transpose + split
    k_reduce_tsplit<<<dim3(d / 32, d / 32), tb>>>(Gpart, MTh, MTl);
    // idx 7: out = norm @ M — A hi only (AlBh dropped; B lo kept)
    k_mma_gemm<<<dim3(d / 128, n / 128, 1), 256, NSTAGE * STAGE_BYTES>>>(
        nh, nh, MTh, MTl, out, d, d, d, 0, 0, 0);
}

// round 13
// speedup vs baseline: 5.0931x; 1.2053x over previous
#include <cuda_runtime.h>
#include <cuda_fp16.h>
#include <math.h>
#include <stdint.h>

#define NROWS 8192
#define DDIM  1024
#define ZSPLIT 4     // GEMM1 k-split
#define ZSPLIT2 2    // GEMM2 k-split

// ---------------- scratch (device globals; no allocation) ----------------
__device__ float  g_invs  [NROWS];
__device__ __half g_norm_h[NROWS * DDIM];
__device__ __half g_normT_h[DDIM * NROWS];
__device__ __half g_normT_l[DDIM * NROWS];
__device__ __half g_xT_h  [DDIM * NROWS];
__device__ __half g_xT_l  [DDIM * NROWS];
__device__ __half g_WT_h  [DDIM * DDIM];
__device__ __half g_WT_l  [DDIM * DDIM];
__device__ float  g_Gpart [ZSPLIT * DDIM * DDIM];   // reused for M partials
__device__ __half g_G_h   [DDIM * DDIM];
__device__ __half g_G_l   [DDIM * DDIM];
__device__ __half g_MT_h  [DDIM * DDIM];
__device__ __half g_MT_l  [DDIM * DDIM];

// ---------------- PTX helpers ----------------
__device__ __forceinline__ uint32_t smem_u32(const void* p) {
    uint32_t a;
    asm("{ .reg .u64 t; cvta.to.shared.u64 t, %1; cvt.u32.u64 %0, t; }" : "=r"(a) : "l"(p));
    return a;
}
__device__ __forceinline__ void cp16(uint32_t dst, const void* src) {
    asm volatile("cp.async.cg.shared.global [%0], [%1], 16;" :: "r"(dst), "l"(src));
}
#define CP_COMMIT() asm volatile("cp.async.commit_group;" ::: "memory")
#define CP_WAIT1()  asm volatile("cp.async.wait_group 1;" ::: "memory")

__device__ __forceinline__ void ldsm4(uint32_t* r, uint32_t addr) {
    asm volatile("ldmatrix.sync.aligned.m8n8.x4.shared.b16 {%0,%1,%2,%3}, [%4];"
                 : "=r"(r[0]), "=r"(r[1]), "=r"(r[2]), "=r"(r[3]) : "r"(addr));
}
__device__ __forceinline__ void mma16816(float* c, const uint32_t* a, const uint32_t* b) {
    asm volatile(
        "mma.sync.aligned.m16n8k16.row.col.f32.f16.f16.f32 "
        "{%0,%1,%2,%3}, {%4,%5,%6,%7}, {%8,%9}, {%0,%1,%2,%3};"
        : "+f"(c[0]), "+f"(c[1]), "+f"(c[2]), "+f"(c[3])
        : "r"(a[0]), "r"(a[1]), "r"(a[2]), "r"(a[3]), "r"(b[0]), "r"(b[1]));
}
__device__ __forceinline__ void mma16816_f16(uint32_t* c, const uint32_t* a, const uint32_t* b) {
    asm volatile(
        "mma.sync.aligned.m16n8k16.row.col.f16.f16.f16.f16 "
        "{%0,%1}, {%2,%3,%4,%5}, {%6,%7}, {%0,%1};"
        : "+r"(c[0]), "+r"(c[1])
        : "r"(a[0]), "r"(a[1]), "r"(a[2]), "r"(a[3]), "r"(b[0]), "r"(b[1]));
}

// ---------------- prep kernels ----------------
__global__ void k_rownorm(const float* __restrict__ x, float* __restrict__ invs) {
    int wid = threadIdx.x >> 5, lane = threadIdx.x & 31;
    int row = blockIdx.x * 8 + wid;
    const float4* xr = (const float4*)(x + (size_t)row * DDIM);
    float s = 0.0f;
    #pragma unroll
    for (int j = 0; j < 8; j++) {
        float4 v = xr[lane + 32 * j];
        s += v.x * v.x + v.y * v.y + v.z * v.z + v.w * v.w;
    }
    #pragma unroll
    for (int o = 16; o > 0; o >>= 1) s += __shfl_xor_sync(0xffffffffu, s, o);
    if (lane == 0) invs[row] = 1.0f / fmaxf(sqrtf(s), 1e-12f);
}

__global__ void k_prep(const float* __restrict__ x, const float* __restrict__ invs,
                       __half* __restrict__ nh,
                       __half* __restrict__ xTh, __half* __restrict__ xTl,
                       __half* __restrict__ nTh, __half* __restrict__ nTl) {
    __shared__ float tile[32][33];
    __shared__ float sinv[32];
    int c0 = blockIdx.x * 32, r0 = blockIdx.y * 32;
    if (threadIdx.y == 0) sinv[threadIdx.x] = invs[r0 + threadIdx.x];
    #pragma unroll
    for (int i = threadIdx.y; i < 32; i += 8)
        tile[i][threadIdx.x] = x[(size_t)(r0 + i) * DDIM + c0 + threadIdx.x];
    __syncthreads();
    #pragma unroll
    for (int i = threadIdx.y; i < 32; i += 8) {
        float v = tile[i][threadIdx.x] * sinv[i];
        nh[(size_t)(r0 + i) * DDIM + c0 + threadIdx.x] = __float2half_rn(v);
    }
    float is = sinv[threadIdx.x];
    #pragma unroll
    for (int i = threadIdx.y; i < 32; i += 8) {
        float v = tile[threadIdx.x][i];
        size_t o = (size_t)(c0 + i) * NROWS + r0 + threadIdx.x;
        __half xh = __float2half_rn(v);
        xTh[o] = xh;
        xTl[o] = __float2half_rn(v - __half2float(xh));
        float nv = v * is;
        __half nhh = __float2half_rn(nv);
        nTh[o] = nhh;
        nTl[o] = __float2half_rn(nv - __half2float(nhh));
    }
}

__global__ void k_tsplit(const float* __restrict__ src,
                         __half* __restrict__ dh, __half* __restrict__ dl,
                         int R, int C) {
    __shared__ float tile[32][33];
    int c0 = blockIdx.x * 32, r0 = blockIdx.y * 32;
    #pragma unroll
    for (int i = threadIdx.y; i < 32; i += 8)
        tile[i][threadIdx.x] = src[(size_t)(r0 + i) * C + c0 + threadIdx.x];
    __syncthreads();
    #pragma unroll
    for (int i = threadIdx.y; i < 32; i += 8) {
        float v = tile[threadIdx.x][i];
        __half h = __float2half_rn(v);
        size_t o = (size_t)(c0 + i) * R + r0 + threadIdx.x;
        dh[o] = h;
        dl[o] = __float2half_rn(v - __half2float(h));
    }
}

__global__ void k_reduce_split_sym(const float* __restrict__ p,
                                   __half* __restrict__ dh, __half* __restrict__ dl) {
    const int n = DDIM * DDIM;
    int c0 = blockIdx.x * 32, r0 = blockIdx.y * 32;
    if ((blockIdx.y >> 2) <= (blockIdx.x >> 2)) {
        #pragma unroll
        for (int i = threadIdx.y; i < 32; i += 8) {
            size_t o = (size_t)(r0 + i) * DDIM + c0 + threadIdx.x;
            float s = 0.0f;
            #pragma unroll
            for (int z = 0; z < ZSPLIT; z++) s += p[o + (size_t)z * n];
            __half h = __float2half_rn(s);
            dh[o] = h;
            dl[o] = __float2half_rn(s - __half2float(h));
        }
    } else {
        __shared__ float tile[32][33];
        #pragma unroll
        for (int i = threadIdx.y; i < 32; i += 8) {
            size_t o = (size_t)(c0 + i) * DDIM + r0 + threadIdx.x;
            float s = 0.0f;
            #pragma unroll
            for (int z = 0; z < ZSPLIT; z++) s += p[o + (size_t)z * n];
            tile[i][threadIdx.x] = s;
        }
        __syncthreads();
        #pragma unroll
        for (int i = threadIdx.y; i < 32; i += 8) {
            float v = tile[threadIdx.x][i];
            size_t o = (size_t)(r0 + i) * DDIM + c0 + threadIdx.x;
            __half h = __float2half_rn(v);
            dh[o] = h;
            dl[o] = __float2half_rn(v - __half2float(h));
        }
    }
}

__global__ void k_reduce_tsplit(const float* __restrict__ p,
                                __half* __restrict__ dh, __half* __restrict__ dl) {
    __shared__ float tile[32][33];
    const int n = DDIM * DDIM;
    int c0 = blockIdx.x * 32, r0 = blockIdx.y * 32;
    #pragma unroll
    for (int i = threadIdx.y; i < 32; i += 8) {
        size_t o = (size_t)(r0 + i) * DDIM + c0 + threadIdx.x;
        float s = 0.0f;
        #pragma unroll
        for (int z = 0; z < ZSPLIT2; z++) s += p[o + (size_t)z * n];
        tile[i][threadIdx.x] = s;
    }
    __syncthreads();
    #pragma unroll
    for (int i = threadIdx.y; i < 32; i += 8) {
        float v = tile[threadIdx.x][i];
        __half h = __float2half_rn(v);
        size_t o = (size_t)(c0 + i) * DDIM + r0 + threadIdx.x;
        dh[o] = h;
        dl[o] = __float2half_rn(v - __half2float(h));
    }
}

// ---------------- fp16 HMMA GEMM, 512 threads (4 warps/SMSP) ----------------
// CTA tile 128x128, BK=64, 3-stage cp.async, warp grid 4x4 (warp tile 32x32).
// USE_AL template: 1 = AhBh(f32) + AlBh + AhBl (f16); 0 = AhBh + AhBl.
#define STAGE_BYTES 65536
#define NSTAGE 3

template<int USE_AL>
__global__ __launch_bounds__(512, 1) void k_mma_gemm(
    const __half* __restrict__ Ah, const __half* __restrict__ Al,
    const __half* __restrict__ Bh, const __half* __restrict__ Bl,
    float* __restrict__ C, int ldk, int kPerZ, int ldc, int partStride, int triMap)
{
    int bi, bj;
    if (triMap) {
        int p = blockIdx.x;
        int i = 0, rem = p;
        #pragma unroll
        for (int r = 0; r < 8; r++) {
            int len = 8 - r;
            if (rem >= len && i == r) { rem -= len; i = r + 1; }
        }
        bi = i; bj = i + rem;
    } else {
        bi = blockIdx.y; bj = blockIdx.x;
    }

    extern __shared__ char smem[];
    uint32_t sbase = smem_u32(smem);
    int t = threadIdx.x;
    int lane = t & 31, w = t >> 5;
    int wm = w >> 2, wn = w & 3;                 // warp grid 4 x 4
    int i0 = bi * 128, j0 = bj * 128;
    int kbase = blockIdx.z * kPerZ;
    int T = kPerZ >> 6;                          // k-tiles of 64

    int g = lane >> 3, lr = lane & 7;
    int rA = wm * 32 + ((g & 1) << 3) + lr;      // warp covers 32 M rows
    uint32_t aRow = sbase + (uint32_t)rA * 128;
    uint32_t sA = (uint32_t)(rA & 7);
    uint32_t cAoff = (uint32_t)(g >> 1);
    int rB = wn * 32 + ((g >> 1) << 3) + lr;     // warp covers 32 N cols
    uint32_t bRow = sbase + 16384u + (uint32_t)rB * 128;
    uint32_t sB = (uint32_t)(rB & 7);
    uint32_t cBoff = (uint32_t)(g & 1);

    float acc[2][4][4];
    uint32_t corr[2][4][2];
    #pragma unroll
    for (int a = 0; a < 2; a++)
        #pragma unroll
        for (int b = 0; b < 4; b++) {
            #pragma unroll
            for (int c = 0; c < 4; c++) acc[a][b][c] = 0.0f;
            corr[a][b][0] = 0u; corr[a][b][1] = 0u;
        }

    // single-buffered fragments (latency hidden by 4 warps/SMSP)
    uint32_t aH[2][4], aL[2][4], bH[8], bL[8];

    auto load_stage = [&](int kt, int buf) {
        int kk = kbase + kt * 64;
        uint32_t dstBase = sbase + (uint32_t)buf * STAGE_BYTES;
        #pragma unroll
        for (int i = 0; i < 8; i++) {
            int e = t + i * 512;                 // 0..4095
            int sub = e >> 11;                   // k-half
            int rem = e & 2047;
            int tile = rem >> 10;                // 0=A, 1=B
            int idx = rem & 1023;
            int r = idx >> 3, l = idx & 7;
            if (!USE_AL && tile == 0 && l >= 4) continue;   // compile-time prune
            uint32_t phys = dstBase + ((uint32_t)sub << 15) + ((uint32_t)tile << 14)
                          + (uint32_t)r * 128u + (uint32_t)(((l ^ (r & 7)) << 4));
            int kofs = kk + sub * 32 + (l & 3) * 8;
            const __half* srcp;
            if (tile == 0) {
                srcp = (l < 4 ? Ah : Al) + (size_t)(i0 + r) * ldk + kofs;
            } else {
                srcp = (l < 4 ? Bh : Bl) + (size_t)(j0 + r) * ldk + kofs;
            }
            cp16(phys, srcp);
        }
        CP_COMMIT();
    };

    load_stage(0, 0);

    int bufCur = 0;
    for (int kt = 0; kt < T; kt++) {
        if (kt + 1 < T) load_stage(kt + 1, bufCur + 1 == NSTAGE ? 0 : bufCur + 1);
        else CP_COMMIT();
        CP_WAIT1();
        __syncthreads();
        uint32_t stOff = (uint32_t)bufCur * STAGE_BYTES;

        #pragma unroll
        for (int ks = 0; ks < 4; ks++) {
            uint32_t so = stOff + ((uint32_t)(ks >> 1) << 15);
            uint32_t cbH = (uint32_t)((ks & 1) * 2);
            uint32_t cbL = cbH + 4;
            #pragma unroll
            for (int mt = 0; mt < 2; mt++) {
                uint32_t rowa = aRow + so + (uint32_t)(mt * 16) * 128u;
                ldsm4(aH[mt], rowa + (((cbH + cAoff) ^ sA) << 4));
                if (USE_AL) ldsm4(aL[mt], rowa + (((cbL + cAoff) ^ sA) << 4));
            }
            #pragma unroll
            for (int nt = 0; nt < 2; nt++) {
                uint32_t rowb = bRow + so + (uint32_t)(nt * 16) * 128u;
                ldsm4(&bH[nt * 4], rowb + (((cbH + cBoff) ^ sB) << 4));
                ldsm4(&bL[nt * 4], rowb + (((cbL + cBoff) ^ sB) << 4));
            }
            #pragma unroll
            for (int mt = 0; mt < 2; mt++) {
                #pragma unroll
                for (int j = 0; j < 4; j++) {
                    mma16816(acc[mt][j], aH[mt], &bH[j * 2]);
                    if (USE_AL) mma16816_f16(corr[mt][j], aL[mt], &bH[j * 2]);
                    mma16816_f16(corr[mt][j], aH[mt], &bL[j * 2]);
                }
            }
        }
        bufCur = bufCur + 1 == NSTAGE ? 0 : bufCur + 1;
    }

    // ---- epilogue ----
    float* Cz = C + (size_t)blockIdx.z * partStride;
    int qid = lane >> 2, tc = lane & 3;
    #pragma unroll
    for (int mt = 0; mt < 2; mt++) {
        int r0 = i0 + wm * 32 + mt * 16 + qid;
        #pragma unroll
        for (int j = 0; j < 4; j++) {
            __half2 p0 = *(__half2*)&corr[mt][j][0];
            __half2 p1 = *(__half2*)&corr[mt][j][1];
            int cc = j0 + wn * 32 + j * 8 + tc * 2;
            *(float2*)&Cz[(size_t)r0 * ldc + cc] =
                make_float2(acc[mt][j][0] + __half2float(p0.x),
                            acc[mt][j][1] + __half2float(p0.y));
            *(float2*)&Cz[(size_t)(r0 + 8) * ldc + cc] =
                make_float2(acc[mt][j][2] + __half2float(p1.x),
                            acc[mt][j][3] + __half2float(p1.y));
        }
    }
}

// ---------------- launch ----------------
extern "C" void kernel_launch(void* const* d_in, const int* in_sizes, int n_in,
                              void* d_out, int out_size)
{
    const float* x = (const float*)d_in[0];   // [n, d]
    const float* w = (const float*)d_in[1];   // [d, d]
    float* out = (float*)d_out;               // [n, d]

    int d = (int)(sqrt((double)in_sizes[1]) + 0.5);
    int n = in_sizes[0] / d;

    float *invs, *Gpart;
    __half *nh, *nTh, *nTl, *xTh, *xTl, *WTh, *WTl, *Gh, *Gl, *MTh, *MTl;
    cudaGetSymbolAddress((void**)&invs, g_invs);
    cudaGetSymbolAddress((void**)&nh, g_norm_h);
    cudaGetSymbolAddress((void**)&nTh, g_normT_h); cudaGetSymbolAddress((void**)&nTl, g_normT_l);
    cudaGetSymbolAddress((void**)&xTh, g_xT_h);    cudaGetSymbolAddress((void**)&xTl, g_xT_l);
    cudaGetSymbolAddress((void**)&WTh, g_WT_h);    cudaGetSymbolAddress((void**)&WTl, g_WT_l);
    cudaGetSymbolAddress((void**)&Gpart, g_Gpart);
    cudaGetSymbolAddress((void**)&Gh, g_G_h);      cudaGetSymbolAddress((void**)&Gl, g_G_l);
    cudaGetSymbolAddress((void**)&MTh, g_MT_h);    cudaGetSymbolAddress((void**)&MTl, g_MT_l);

    cudaFuncSetAttribute(k_mma_gemm<1>, cudaFuncAttributeMaxDynamicSharedMemorySize,
                         NSTAGE * STAGE_BYTES);
    cudaFuncSetAttribute(k_mma_gemm<0>, cudaFuncAttributeMaxDynamicSharedMemorySize,
                         NSTAGE * STAGE_BYTES);

    dim3 tb(32, 8);

    // idx 0: row norms
    k_rownorm<<<n / 8, 256>>>(x, invs);
    // idx 1: fused prep (nh + xT,nT hi/lo)
    k_prep<<<dim3(d / 32, n / 32), tb>>>(x, invs, nh, xTh, xTl, nTh, nTl);
    // idx 2: W transpose+split
    k_tsplit<<<dim3(d / 32, d / 32), tb>>>(w, WTh, WTl, d, d);
    // idx 3: G = norm^T @ x — upper-tri grid (36 pairs), ZSPLIT k-split; PROFILED
    k_mma_gemm<1><<<dim3(36, 1, ZSPLIT), 512, NSTAGE * STAGE_BYTES>>>(
        nTh, nTl, xTh, xTl, Gpart, n, n / ZSPLIT, d, d * d, 1);
    // idx 4: reduce G partials + mirror lower + split
    k_reduce_split_sym<<<dim3(d / 32, d / 32), tb>>>(Gpart, Gh, Gl);
    // idx 5: M partials = G @ W (K split by ZSPLIT2; reuse Gpart)
    k_mma_gemm<1><<<dim3(d / 128, d / 128, ZSPLIT2), 512, NSTAGE * STAGE_BYTES>>>(
        Gh, Gl, WTh, WTl, Gpart, d, d / ZSPLIT2, d, d * d, 0);
    // idx 6: reduce M partials + transpose + split
    k_reduce_tsplit<<<dim3(d / 32, d / 32), tb>>>(Gpart, MTh, MTl);
    // idx 7: out = norm @ M — A hi only (AlBh dropped; B lo kept)
    k_mma_gemm<0><<<dim3(d / 128, n / 128, 1), 512, NSTAGE * STAGE_BYTES>>>(
        nh, nh, MTh, MTl, out, d, d, d, 0, 0);
}

// round 15
// speedup vs baseline: 5.6517x; 1.1097x over previous
#include <cuda_runtime.h>
#include <cuda_fp16.h>
#include <math.h>
#include <stdint.h>

#define NROWS 8192
#define DDIM  1024
#define ZSPLIT 4     // GEMM1 k-split
#define ZSPLIT2 2    // GEMM2 k-split

// ---------------- scratch (device globals; no allocation) ----------------
__device__ float  g_invs  [NROWS];
__device__ __half g_norm_h[NROWS * DDIM];
__device__ __half g_normT_h[DDIM * NROWS];
__device__ __half g_xT_h  [DDIM * NROWS];
__device__ __half g_xT_l  [DDIM * NROWS];
__device__ __half g_WT_h  [DDIM * DDIM];
__device__ __half g_WT_l  [DDIM * DDIM];
__device__ float  g_Gpart [ZSPLIT * DDIM * DDIM];   // reused for M partials
__device__ __half g_G_h   [DDIM * DDIM];
__device__ __half g_G_l   [DDIM * DDIM];
__device__ __half g_MT_h  [DDIM * DDIM];
__device__ __half g_MT_l  [DDIM * DDIM];

// ---------------- PTX helpers ----------------
__device__ __forceinline__ uint32_t smem_u32(const void* p) {
    uint32_t a;
    asm("{ .reg .u64 t; cvta.to.shared.u64 t, %1; cvt.u32.u64 %0, t; }" : "=r"(a) : "l"(p));
    return a;
}
__device__ __forceinline__ void cp16(uint32_t dst, const void* src) {
    asm volatile("cp.async.cg.shared.global [%0], [%1], 16;" :: "r"(dst), "l"(src));
}
#define CP_COMMIT() asm volatile("cp.async.commit_group;" ::: "memory")
#define CP_WAIT1()  asm volatile("cp.async.wait_group 1;" ::: "memory")

__device__ __forceinline__ void ldsm4(uint32_t* r, uint32_t addr) {
    asm volatile("ldmatrix.sync.aligned.m8n8.x4.shared.b16 {%0,%1,%2,%3}, [%4];"
                 : "=r"(r[0]), "=r"(r[1]), "=r"(r[2]), "=r"(r[3]) : "r"(addr));
}
__device__ __forceinline__ void mma16816(float* c, const uint32_t* a, const uint32_t* b) {
    asm volatile(
        "mma.sync.aligned.m16n8k16.row.col.f32.f16.f16.f32 "
        "{%0,%1,%2,%3}, {%4,%5,%6,%7}, {%8,%9}, {%0,%1,%2,%3};"
        : "+f"(c[0]), "+f"(c[1]), "+f"(c[2]), "+f"(c[3])
        : "r"(a[0]), "r"(a[1]), "r"(a[2]), "r"(a[3]), "r"(b[0]), "r"(b[1]));
}
__device__ __forceinline__ void mma16816_f16(uint32_t* c, const uint32_t* a, const uint32_t* b) {
    asm volatile(
        "mma.sync.aligned.m16n8k16.row.col.f16.f16.f16.f16 "
        "{%0,%1}, {%2,%3,%4,%5}, {%6,%7}, {%0,%1};"
        : "+r"(c[0]), "+r"(c[1])
        : "r"(a[0]), "r"(a[1]), "r"(a[2]), "r"(a[3]), "r"(b[0]), "r"(b[1]));
}

// ---------------- prep kernels ----------------
__global__ void k_rownorm(const float* __restrict__ x, float* __restrict__ invs) {
    int wid = threadIdx.x >> 5, lane = threadIdx.x & 31;
    int row = blockIdx.x * 8 + wid;
    const float4* xr = (const float4*)(x + (size_t)row * DDIM);
    float s = 0.0f;
    #pragma unroll
    for (int j = 0; j < 8; j++) {
        float4 v = xr[lane + 32 * j];
        s += v.x * v.x + v.y * v.y + v.z * v.z + v.w * v.w;
    }
    #pragma unroll
    for (int o = 16; o > 0; o >>= 1) s += __shfl_xor_sync(0xffffffffu, s, o);
    if (lane == 0) invs[row] = 1.0f / fmaxf(sqrtf(s), 1e-12f);
}

// x tile -> nh (straight, hi only) + xT hi/lo + nT hi (transposed)
__global__ void k_prep(const float* __restrict__ x, const float* __restrict__ invs,
                       __half* __restrict__ nh,
                       __half* __restrict__ xTh, __half* __restrict__ xTl,
                       __half* __restrict__ nTh) {
    __shared__ float tile[32][33];
    __shared__ float sinv[32];
    int c0 = blockIdx.x * 32, r0 = blockIdx.y * 32;
    if (threadIdx.y == 0) sinv[threadIdx.x] = invs[r0 + threadIdx.x];
    #pragma unroll
    for (int i = threadIdx.y; i < 32; i += 8)
        tile[i][threadIdx.x] = x[(size_t)(r0 + i) * DDIM + c0 + threadIdx.x];
    __syncthreads();
    #pragma unroll
    for (int i = threadIdx.y; i < 32; i += 8) {
        float v = tile[i][threadIdx.x] * sinv[i];
        nh[(size_t)(r0 + i) * DDIM + c0 + threadIdx.x] = __float2half_rn(v);
    }
    float is = sinv[threadIdx.x];
    #pragma unroll
    for (int i = threadIdx.y; i < 32; i += 8) {
        float v = tile[threadIdx.x][i];
        size_t o = (size_t)(c0 + i) * NROWS + r0 + threadIdx.x;
        __half xh = __float2half_rn(v);
        xTh[o] = xh;
        xTl[o] = __float2half_rn(v - __half2float(xh));
        nTh[o] = __float2half_rn(v * is);
    }
}

__global__ void k_tsplit(const float* __restrict__ src,
                         __half* __restrict__ dh, __half* __restrict__ dl,
                         int R, int C) {
    __shared__ float tile[32][33];
    int c0 = blockIdx.x * 32, r0 = blockIdx.y * 32;
    #pragma unroll
    for (int i = threadIdx.y; i < 32; i += 8)
        tile[i][threadIdx.x] = src[(size_t)(r0 + i) * C + c0 + threadIdx.x];
    __syncthreads();
    #pragma unroll
    for (int i = threadIdx.y; i < 32; i += 8) {
        float v = tile[threadIdx.x][i];
        __half h = __float2half_rn(v);
        size_t o = (size_t)(c0 + i) * R + r0 + threadIdx.x;
        dh[o] = h;
        dl[o] = __float2half_rn(v - __half2float(h));
    }
}

__global__ void k_reduce_split_sym(const float* __restrict__ p,
                                   __half* __restrict__ dh, __half* __restrict__ dl) {
    const int n = DDIM * DDIM;
    int c0 = blockIdx.x * 32, r0 = blockIdx.y * 32;
    if ((blockIdx.y >> 2) <= (blockIdx.x >> 2)) {
        #pragma unroll
        for (int i = threadIdx.y; i < 32; i += 8) {
            size_t o = (size_t)(r0 + i) * DDIM + c0 + threadIdx.x;
            float s = 0.0f;
            #pragma unroll
            for (int z = 0; z < ZSPLIT; z++) s += p[o + (size_t)z * n];
            __half h = __float2half_rn(s);
            dh[o] = h;
            dl[o] = __float2half_rn(s - __half2float(h));
        }
    } else {
        __shared__ float tile[32][33];
        #pragma unroll
        for (int i = threadIdx.y; i < 32; i += 8) {
            size_t o = (size_t)(c0 + i) * DDIM + r0 + threadIdx.x;
            float s = 0.0f;
            #pragma unroll
            for (int z = 0; z < ZSPLIT; z++) s += p[o + (size_t)z * n];
            tile[i][threadIdx.x] = s;
        }
        __syncthreads();
        #pragma unroll
        for (int i = threadIdx.y; i < 32; i += 8) {
            float v = tile[threadIdx.x][i];
            size_t o = (size_t)(r0 + i) * DDIM + c0 + threadIdx.x;
            __half h = __float2half_rn(v);
            dh[o] = h;
            dl[o] = __float2half_rn(v - __half2float(h));
        }
    }
}

__global__ void k_reduce_tsplit(const float* __restrict__ p,
                                __half* __restrict__ dh, __half* __restrict__ dl) {
    __shared__ float tile[32][33];
    const int n = DDIM * DDIM;
    int c0 = blockIdx.x * 32, r0 = blockIdx.y * 32;
    #pragma unroll
    for (int i = threadIdx.y; i < 32; i += 8) {
        size_t o = (size_t)(r0 + i) * DDIM + c0 + threadIdx.x;
        float s = 0.0f;
        #pragma unroll
        for (int z = 0; z < ZSPLIT2; z++) s += p[o + (size_t)z * n];
        tile[i][threadIdx.x] = s;
    }
    __syncthreads();
    #pragma unroll
    for (int i = threadIdx.y; i < 32; i += 8) {
        float v = tile[threadIdx.x][i];
        __half h = __float2half_rn(v);
        size_t o = (size_t)(c0 + i) * DDIM + r0 + threadIdx.x;
        dh[o] = h;
        dl[o] = __float2half_rn(v - __half2float(h));
    }
}

// ---------------- fp16 HMMA GEMM, 512 threads (4 warps/SMSP) ----------------
// CTA tile 128x128, BK=64, 3-stage cp.async, warp grid 4x4 (warp tile 32x32).
// USE_AL template: 1 = AhBh(f32) + AlBh + AhBl (f16); 0 = AhBh + AhBl.
#define STAGE_BYTES 65536
#define NSTAGE 3

template<int USE_AL>
__global__ __launch_bounds__(512, 1) void k_mma_gemm(
    const __half* __restrict__ Ah, const __half* __restrict__ Al,
    const __half* __restrict__ Bh, const __half* __restrict__ Bl,
    float* __restrict__ C, int ldk, int kPerZ, int ldc, int partStride, int triMap)
{
    int bi, bj;
    if (triMap) {
        int p = blockIdx.x;
        int i = 0, rem = p;
        #pragma unroll
        for (int r = 0; r < 8; r++) {
            int len = 8 - r;
            if (rem >= len && i == r) { rem -= len; i = r + 1; }
        }
        bi = i; bj = i + rem;
    } else {
        bi = blockIdx.y; bj = blockIdx.x;
    }

    extern __shared__ char smem[];
    uint32_t sbase = smem_u32(smem);
    int t = threadIdx.x;
    int lane = t & 31, w = t >> 5;
    int wm = w >> 2, wn = w & 3;                 // warp grid 4 x 4
    int i0 = bi * 128, j0 = bj * 128;
    int kbase = blockIdx.z * kPerZ;
    int T = kPerZ >> 6;                          // k-tiles of 64

    int g = lane >> 3, lr = lane & 7;
    int rA = wm * 32 + ((g & 1) << 3) + lr;      // warp covers 32 M rows
    uint32_t aRow = sbase + (uint32_t)rA * 128;
    uint32_t sA = (uint32_t)(rA & 7);
    uint32_t cAoff = (uint32_t)(g >> 1);
    int rB = wn * 32 + ((g >> 1) << 3) + lr;     // warp covers 32 N cols
    uint32_t bRow = sbase + 16384u + (uint32_t)rB * 128;
    uint32_t sB = (uint32_t)(rB & 7);
    uint32_t cBoff = (uint32_t)(g & 1);

    float acc[2][4][4];
    uint32_t corr[2][4][2];
    #pragma unroll
    for (int a = 0; a < 2; a++)
        #pragma unroll
        for (int b = 0; b < 4; b++) {
            #pragma unroll
            for (int c = 0; c < 4; c++) acc[a][b][c] = 0.0f;
            corr[a][b][0] = 0u; corr[a][b][1] = 0u;
        }

    // single-buffered fragments (latency hidden by 4 warps/SMSP)
    uint32_t aH[2][4], aL[2][4], bH[8], bL[8];

    auto load_stage = [&](int kt, int buf) {
        int kk = kbase + kt * 64;
        uint32_t dstBase = sbase + (uint32_t)buf * STAGE_BYTES;
        #pragma unroll
        for (int i = 0; i < 8; i++) {
            int e = t + i * 512;                 // 0..4095
            int sub = e >> 11;                   // k-half
            int rem = e & 2047;
            int tile = rem >> 10;                // 0=A, 1=B
            int idx = rem & 1023;
            int r = idx >> 3, l = idx & 7;
            if (!USE_AL && tile == 0 && l >= 4) continue;   // compile-time prune
            uint32_t phys = dstBase + ((uint32_t)sub << 15) + ((uint32_t)tile << 14)
                          + (uint32_t)r * 128u + (uint32_t)(((l ^ (r & 7)) << 4));
            int kofs = kk + sub * 32 + (l & 3) * 8;
            const __half* srcp;
            if (tile == 0) {
                srcp = (l < 4 ? Ah : Al) + (size_t)(i0 + r) * ldk + kofs;
            } else {
                srcp = (l < 4 ? Bh : Bl) + (size_t)(j0 + r) * ldk + kofs;
            }
            cp16(phys, srcp);
        }
        CP_COMMIT();
    };

    load_stage(0, 0);

    int bufCur = 0;
    for (int kt = 0; kt < T; kt++) {
        if (kt + 1 < T) load_stage(kt + 1, bufCur + 1 == NSTAGE ? 0 : bufCur + 1);
        else CP_COMMIT();
        CP_WAIT1();
        __syncthreads();
        uint32_t stOff = (uint32_t)bufCur * STAGE_BYTES;

        #pragma unroll
        for (int ks = 0; ks < 4; ks++) {
            uint32_t so = stOff + ((uint32_t)(ks >> 1) << 15);
            uint32_t cbH = (uint32_t)((ks & 1) * 2);
            uint32_t cbL = cbH + 4;
            #pragma unroll
            for (int mt = 0; mt < 2; mt++) {
                uint32_t rowa = aRow + so + (uint32_t)(mt * 16) * 128u;
                ldsm4(aH[mt], rowa + (((cbH + cAoff) ^ sA) << 4));
                if (USE_AL) ldsm4(aL[mt], rowa + (((cbL + cAoff) ^ sA) << 4));
            }
            #pragma unroll
            for (int nt = 0; nt < 2; nt++) {
                uint32_t rowb = bRow + so + (uint32_t)(nt * 16) * 128u;
                ldsm4(&bH[nt * 4], rowb + (((cbH + cBoff) ^ sB) << 4));
                ldsm4(&bL[nt * 4], rowb + (((cbL + cBoff) ^ sB) << 4));
            }
            #pragma unroll
            for (int mt = 0; mt < 2; mt++) {
                #pragma unroll
                for (int j = 0; j < 4; j++) {
                    mma16816(acc[mt][j], aH[mt], &bH[j * 2]);
                    if (USE_AL) mma16816_f16(corr[mt][j], aL[mt], &bH[j * 2]);
                    mma16816_f16(corr[mt][j], aH[mt], &bL[j * 2]);
                }
            }
        }
        bufCur = bufCur + 1 == NSTAGE ? 0 : bufCur + 1;
    }

    // ---- epilogue ----
    float* Cz = C + (size_t)blockIdx.z * partStride;
    int qid = lane >> 2, tc = lane & 3;
    #pragma unroll
    for (int mt = 0; mt < 2; mt++) {
        int r0 = i0 + wm * 32 + mt * 16 + qid;
        #pragma unroll
        for (int j = 0; j < 4; j++) {
            __half2 p0 = *(__half2*)&corr[mt][j][0];
            __half2 p1 = *(__half2*)&corr[mt][j][1];
            int cc = j0 + wn * 32 + j * 8 + tc * 2;
            *(float2*)&Cz[(size_t)r0 * ldc + cc] =
                make_float2(acc[mt][j][0] + __half2float(p0.x),
                            acc[mt][j][1] + __half2float(p0.y));
            *(float2*)&Cz[(size_t)(r0 + 8) * ldc + cc] =
                make_float2(acc[mt][j][2] + __half2float(p1.x),
                            acc[mt][j][3] + __half2float(p1.y));
        }
    }
}

// ---------------- launch ----------------
extern "C" void kernel_launch(void* const* d_in, const int* in_sizes, int n_in,
                              void* d_out, int out_size)
{
    const float* x = (const float*)d_in[0];   // [n, d]
    const float* w = (const float*)d_in[1];   // [d, d]
    float* out = (float*)d_out;               // [n, d]

    int d = (int)(sqrt((double)in_sizes[1]) + 0.5);
    int n = in_sizes[0] / d;

    float *invs, *Gpart;
    __half *nh, *nTh, *xTh, *xTl, *WTh, *WTl, *Gh, *Gl, *MTh, *MTl;
    cudaGetSymbolAddress((void**)&invs, g_invs);
    cudaGetSymbolAddress((void**)&nh, g_norm_h);
    cudaGetSymbolAddress((void**)&nTh, g_normT_h);
    cudaGetSymbolAddress((void**)&xTh, g_xT_h);    cudaGetSymbolAddress((void**)&xTl, g_xT_l);
    cudaGetSymbolAddress((void**)&WTh, g_WT_h);    cudaGetSymbolAddress((void**)&WTl, g_WT_l);
    cudaGetSymbolAddress((void**)&Gpart, g_Gpart);
    cudaGetSymbolAddress((void**)&Gh, g_G_h);      cudaGetSymbolAddress((void**)&Gl, g_G_l);
    cudaGetSymbolAddress((void**)&MTh, g_MT_h);    cudaGetSymbolAddress((void**)&MTl, g_MT_l);

    cudaFuncSetAttribute(k_mma_gemm<1>, cudaFuncAttributeMaxDynamicSharedMemorySize,
                         NSTAGE * STAGE_BYTES);
    cudaFuncSetAttribute(k_mma_gemm<0>, cudaFuncAttributeMaxDynamicSharedMemorySize,
                         NSTAGE * STAGE_BYTES);

    dim3 tb(32, 8);

    // idx 0: row norms
    k_rownorm<<<n / 8, 256>>>(x, invs);
    // idx 1: fused prep (nh + xT hi/lo + nT hi)
    k_prep<<<dim3(d / 32, n / 32), tb>>>(x, invs, nh, xTh, xTl, nTh);
    // idx 2: W transpose+split
    k_tsplit<<<dim3(d / 32, d / 32), tb>>>(w, WTh, WTl, d, d);
    // idx 3: G = norm^T @ x — upper-tri grid (36 pairs), ZSPLIT k-split;
    //        A = nT hi only (AlBh dropped), B = xT hi/lo kept; PROFILED
    k_mma_gemm<0><<<dim3(36, 1, ZSPLIT), 512, NSTAGE * STAGE_BYTES>>>(
        nTh, nTh, xTh, xTl, Gpart, n, n / ZSPLIT, d, d * d, 1);
    // idx 4: reduce G partials + mirror lower + split
    k_reduce_split_sym<<<dim3(d / 32, d / 32), tb>>>(Gpart, Gh, Gl);
    // idx 5: M partials = G @ W (full 3-term; K split by ZSPLIT2; reuse Gpart)
    k_mma_gemm<1><<<dim3(d / 128, d / 128, ZSPLIT2), 512, NSTAGE * STAGE_BYTES>>>(
        Gh, Gl, WTh, WTl, Gpart, d, d / ZSPLIT2, d, d * d, 0);
    // idx 6: reduce M partials + transpose + split
    k_reduce_tsplit<<<dim3(d / 32, d / 32), tb>>>(Gpart, MTh, MTl);
    // idx 7: out = norm @ M — A hi only (AlBh dropped; B lo kept)
    k_mma_gemm<0><<<dim3(d / 128, n / 128, 1), 512, NSTAGE * STAGE_BYTES>>>(
        nh, nh, MTh, MTl, out, d, d, d, 0, 0);
}

// round 16
// speedup vs baseline: 7.4005x; 1.3094x over previous
#include <cuda_runtime.h>
#include <cuda_fp16.h>
#include <math.h>
#include <stdint.h>

#define NROWS 8192
#define DDIM  1024
#define ZSPLIT 4     // GEMM1 k-split
#define ZSPLIT2 2    // GEMM2 k-split

// ---------------- scratch (device globals; no allocation) ----------------
__device__ float  g_invs  [NROWS];
__device__ __half g_norm_h[NROWS * DDIM];
__device__ __half g_normT_h[DDIM * NROWS];
__device__ __half g_xT_h  [DDIM * NROWS];
__device__ __half g_WT_h  [DDIM * DDIM];
__device__ __half g_WT_l  [DDIM * DDIM];
__device__ float  g_Gpart [ZSPLIT * DDIM * DDIM];   // reused for M partials
__device__ __half g_G_h   [DDIM * DDIM];
__device__ __half g_G_l   [DDIM * DDIM];
__device__ __half g_MT_h  [DDIM * DDIM];

// ---------------- PTX helpers ----------------
__device__ __forceinline__ uint32_t smem_u32(const void* p) {
    uint32_t a;
    asm("{ .reg .u64 t; cvta.to.shared.u64 t, %1; cvt.u32.u64 %0, t; }" : "=r"(a) : "l"(p));
    return a;
}
__device__ __forceinline__ void cp16(uint32_t dst, const void* src) {
    asm volatile("cp.async.cg.shared.global [%0], [%1], 16;" :: "r"(dst), "l"(src));
}
#define CP_COMMIT() asm volatile("cp.async.commit_group;" ::: "memory")
#define CP_WAIT1()  asm volatile("cp.async.wait_group 1;" ::: "memory")

__device__ __forceinline__ void ldsm4(uint32_t* r, uint32_t addr) {
    asm volatile("ldmatrix.sync.aligned.m8n8.x4.shared.b16 {%0,%1,%2,%3}, [%4];"
                 : "=r"(r[0]), "=r"(r[1]), "=r"(r[2]), "=r"(r[3]) : "r"(addr));
}
__device__ __forceinline__ void mma16816(float* c, const uint32_t* a, const uint32_t* b) {
    asm volatile(
        "mma.sync.aligned.m16n8k16.row.col.f32.f16.f16.f32 "
        "{%0,%1,%2,%3}, {%4,%5,%6,%7}, {%8,%9}, {%0,%1,%2,%3};"
        : "+f"(c[0]), "+f"(c[1]), "+f"(c[2]), "+f"(c[3])
        : "r"(a[0]), "r"(a[1]), "r"(a[2]), "r"(a[3]), "r"(b[0]), "r"(b[1]));
}
__device__ __forceinline__ void mma16816_f16(uint32_t* c, const uint32_t* a, const uint32_t* b) {
    asm volatile(
        "mma.sync.aligned.m16n8k16.row.col.f16.f16.f16.f16 "
        "{%0,%1}, {%2,%3,%4,%5}, {%6,%7}, {%0,%1};"
        : "+r"(c[0]), "+r"(c[1])
        : "r"(a[0]), "r"(a[1]), "r"(a[2]), "r"(a[3]), "r"(b[0]), "r"(b[1]));
}

// ---------------- prep kernels ----------------
__global__ void k_rownorm(const float* __restrict__ x, float* __restrict__ invs) {
    int wid = threadIdx.x >> 5, lane = threadIdx.x & 31;
    int row = blockIdx.x * 8 + wid;
    const float4* xr = (const float4*)(x + (size_t)row * DDIM);
    float s = 0.0f;
    #pragma unroll
    for (int j = 0; j < 8; j++) {
        float4 v = xr[lane + 32 * j];
        s += v.x * v.x + v.y * v.y + v.z * v.z + v.w * v.w;
    }
    #pragma unroll
    for (int o = 16; o > 0; o >>= 1) s += __shfl_xor_sync(0xffffffffu, s, o);
    if (lane == 0) invs[row] = 1.0f / fmaxf(sqrtf(s), 1e-12f);
}

// x tile -> nh (straight) + xT hi + nT hi (transposed)
__global__ void k_prep(const float* __restrict__ x, const float* __restrict__ invs,
                       __half* __restrict__ nh,
                       __half* __restrict__ xTh, __half* __restrict__ nTh) {
    __shared__ float tile[32][33];
    __shared__ float sinv[32];
    int c0 = blockIdx.x * 32, r0 = blockIdx.y * 32;
    if (threadIdx.y == 0) sinv[threadIdx.x] = invs[r0 + threadIdx.x];
    #pragma unroll
    for (int i = threadIdx.y; i < 32; i += 8)
        tile[i][threadIdx.x] = x[(size_t)(r0 + i) * DDIM + c0 + threadIdx.x];
    __syncthreads();
    #pragma unroll
    for (int i = threadIdx.y; i < 32; i += 8) {
        float v = tile[i][threadIdx.x] * sinv[i];
        nh[(size_t)(r0 + i) * DDIM + c0 + threadIdx.x] = __float2half_rn(v);
    }
    float is = sinv[threadIdx.x];
    #pragma unroll
    for (int i = threadIdx.y; i < 32; i += 8) {
        float v = tile[threadIdx.x][i];
        size_t o = (size_t)(c0 + i) * NROWS + r0 + threadIdx.x;
        xTh[o] = __float2half_rn(v);
        nTh[o] = __float2half_rn(v * is);
    }
}

__global__ void k_tsplit(const float* __restrict__ src,
                         __half* __restrict__ dh, __half* __restrict__ dl,
                         int R, int C) {
    __shared__ float tile[32][33];
    int c0 = blockIdx.x * 32, r0 = blockIdx.y * 32;
    #pragma unroll
    for (int i = threadIdx.y; i < 32; i += 8)
        tile[i][threadIdx.x] = src[(size_t)(r0 + i) * C + c0 + threadIdx.x];
    __syncthreads();
    #pragma unroll
    for (int i = threadIdx.y; i < 32; i += 8) {
        float v = tile[threadIdx.x][i];
        __half h = __float2half_rn(v);
        size_t o = (size_t)(c0 + i) * R + r0 + threadIdx.x;
        dh[o] = h;
        dl[o] = __float2half_rn(v - __half2float(h));
    }
}

__global__ void k_reduce_split_sym(const float* __restrict__ p,
                                   __half* __restrict__ dh, __half* __restrict__ dl) {
    const int n = DDIM * DDIM;
    int c0 = blockIdx.x * 32, r0 = blockIdx.y * 32;
    if ((blockIdx.y >> 2) <= (blockIdx.x >> 2)) {
        #pragma unroll
        for (int i = threadIdx.y; i < 32; i += 8) {
            size_t o = (size_t)(r0 + i) * DDIM + c0 + threadIdx.x;
            float s = 0.0f;
            #pragma unroll
            for (int z = 0; z < ZSPLIT; z++) s += p[o + (size_t)z * n];
            __half h = __float2half_rn(s);
            dh[o] = h;
            dl[o] = __float2half_rn(s - __half2float(h));
        }
    } else {
        __shared__ float tile[32][33];
        #pragma unroll
        for (int i = threadIdx.y; i < 32; i += 8) {
            size_t o = (size_t)(c0 + i) * DDIM + r0 + threadIdx.x;
            float s = 0.0f;
            #pragma unroll
            for (int z = 0; z < ZSPLIT; z++) s += p[o + (size_t)z * n];
            tile[i][threadIdx.x] = s;
        }
        __syncthreads();
        #pragma unroll
        for (int i = threadIdx.y; i < 32; i += 8) {
            float v = tile[threadIdx.x][i];
            size_t o = (size_t)(r0 + i) * DDIM + c0 + threadIdx.x;
            __half h = __float2half_rn(v);
            dh[o] = h;
            dl[o] = __float2half_rn(v - __half2float(h));
        }
    }
}

// reduce ZSPLIT2 partials of M + transpose -> MT hi only
__global__ void k_reduce_tsplit(const float* __restrict__ p,
                                __half* __restrict__ dh) {
    __shared__ float tile[32][33];
    const int n = DDIM * DDIM;
    int c0 = blockIdx.x * 32, r0 = blockIdx.y * 32;
    #pragma unroll
    for (int i = threadIdx.y; i < 32; i += 8) {
        size_t o = (size_t)(r0 + i) * DDIM + c0 + threadIdx.x;
        float s = 0.0f;
        #pragma unroll
        for (int z = 0; z < ZSPLIT2; z++) s += p[o + (size_t)z * n];
        tile[i][threadIdx.x] = s;
    }
    __syncthreads();
    #pragma unroll
    for (int i = threadIdx.y; i < 32; i += 8) {
        float v = tile[threadIdx.x][i];
        dh[(size_t)(c0 + i) * DDIM + r0 + threadIdx.x] = __float2half_rn(v);
    }
}

// ---------------- fp16 HMMA GEMM, 512 threads (4 warps/SMSP) ----------------
// CTA tile 128x128, BK=64, 3-stage cp.async, warp grid 4x4 (warp tile 32x32).
// Terms: AhBh (f32 acc) always; AlBh if USE_AL; AhBl if USE_BL (f16 acc).
#define STAGE_BYTES 65536
#define NSTAGE 3

template<int USE_AL, int USE_BL>
__global__ __launch_bounds__(512, 1) void k_mma_gemm(
    const __half* __restrict__ Ah, const __half* __restrict__ Al,
    const __half* __restrict__ Bh, const __half* __restrict__ Bl,
    float* __restrict__ C, int ldk, int kPerZ, int ldc, int partStride, int triMap)
{
    constexpr int USE_CORR = USE_AL | USE_BL;
    int bi, bj;
    if (triMap) {
        int p = blockIdx.x;
        int i = 0, rem = p;
        #pragma unroll
        for (int r = 0; r < 8; r++) {
            int len = 8 - r;
            if (rem >= len && i == r) { rem -= len; i = r + 1; }
        }
        bi = i; bj = i + rem;
    } else {
        bi = blockIdx.y; bj = blockIdx.x;
    }

    extern __shared__ char smem[];
    uint32_t sbase = smem_u32(smem);
    int t = threadIdx.x;
    int lane = t & 31, w = t >> 5;
    int wm = w >> 2, wn = w & 3;                 // warp grid 4 x 4
    int i0 = bi * 128, j0 = bj * 128;
    int kbase = blockIdx.z * kPerZ;
    int T = kPerZ >> 6;                          // k-tiles of 64

    int g = lane >> 3, lr = lane & 7;
    int rA = wm * 32 + ((g & 1) << 3) + lr;      // warp covers 32 M rows
    uint32_t aRow = sbase + (uint32_t)rA * 128;
    uint32_t sA = (uint32_t)(rA & 7);
    uint32_t cAoff = (uint32_t)(g >> 1);
    int rB = wn * 32 + ((g >> 1) << 3) + lr;     // warp covers 32 N cols
    uint32_t bRow = sbase + 16384u + (uint32_t)rB * 128;
    uint32_t sB = (uint32_t)(rB & 7);
    uint32_t cBoff = (uint32_t)(g & 1);

    float acc[2][4][4];
    uint32_t corr[2][4][2];
    #pragma unroll
    for (int a = 0; a < 2; a++)
        #pragma unroll
        for (int b = 0; b < 4; b++) {
            #pragma unroll
            for (int c = 0; c < 4; c++) acc[a][b][c] = 0.0f;
            corr[a][b][0] = 0u; corr[a][b][1] = 0u;
        }

    uint32_t aH[2][4], aL[2][4], bH[8], bL[8];

    auto load_stage = [&](int kt, int buf) {
        int kk = kbase + kt * 64;
        uint32_t dstBase = sbase + (uint32_t)buf * STAGE_BYTES;
        #pragma unroll
        for (int i = 0; i < 8; i++) {
            int e = t + i * 512;                 // 0..4095
            int sub = e >> 11;                   // k-half
            int rem = e & 2047;
            int tile = rem >> 10;                // 0=A, 1=B
            int idx = rem & 1023;
            int r = idx >> 3, l = idx & 7;
            if (!USE_AL && tile == 0 && l >= 4) continue;   // skip A-lo
            if (!USE_BL && tile == 1 && l >= 4) continue;   // skip B-lo
            uint32_t phys = dstBase + ((uint32_t)sub << 15) + ((uint32_t)tile << 14)
                          + (uint32_t)r * 128u + (uint32_t)(((l ^ (r & 7)) << 4));
            int kofs = kk + sub * 32 + (l & 3) * 8;
            const __half* srcp;
            if (tile == 0) {
                srcp = (l < 4 ? Ah : Al) + (size_t)(i0 + r) * ldk + kofs;
            } else {
                srcp = (l < 4 ? Bh : Bl) + (size_t)(j0 + r) * ldk + kofs;
            }
            cp16(phys, srcp);
        }
        CP_COMMIT();
    };

    load_stage(0, 0);

    int bufCur = 0;
    for (int kt = 0; kt < T; kt++) {
        if (kt + 1 < T) load_stage(kt + 1, bufCur + 1 == NSTAGE ? 0 : bufCur + 1);
        else CP_COMMIT();
        CP_WAIT1();
        __syncthreads();
        uint32_t stOff = (uint32_t)bufCur * STAGE_BYTES;

        #pragma unroll
        for (int ks = 0; ks < 4; ks++) {
            uint32_t so = stOff + ((uint32_t)(ks >> 1) << 15);
            uint32_t cbH = (uint32_t)((ks & 1) * 2);
            uint32_t cbL = cbH + 4;
            #pragma unroll
            for (int mt = 0; mt < 2; mt++) {
                uint32_t rowa = aRow + so + (uint32_t)(mt * 16) * 128u;
                ldsm4(aH[mt], rowa + (((cbH + cAoff) ^ sA) << 4));
                if (USE_AL) ldsm4(aL[mt], rowa + (((cbL + cAoff) ^ sA) << 4));
            }
            #pragma unroll
            for (int nt = 0; nt < 2; nt++) {
                uint32_t rowb = bRow + so + (uint32_t)(nt * 16) * 128u;
                ldsm4(&bH[nt * 4], rowb + (((cbH + cBoff) ^ sB) << 4));
                if (USE_BL) ldsm4(&bL[nt * 4], rowb + (((cbL + cBoff) ^ sB) << 4));
            }
            #pragma unroll
            for (int mt = 0; mt < 2; mt++) {
                #pragma unroll
                for (int j = 0; j < 4; j++) {
                    mma16816(acc[mt][j], aH[mt], &bH[j * 2]);
                    if (USE_AL) mma16816_f16(corr[mt][j], aL[mt], &bH[j * 2]);
                    if (USE_BL) mma16816_f16(corr[mt][j], aH[mt], &bL[j * 2]);
                }
            }
        }
        bufCur = bufCur + 1 == NSTAGE ? 0 : bufCur + 1;
    }

    // ---- epilogue ----
    float* Cz = C + (size_t)blockIdx.z * partStride;
    int qid = lane >> 2, tc = lane & 3;
    #pragma unroll
    for (int mt = 0; mt < 2; mt++) {
        int r0 = i0 + wm * 32 + mt * 16 + qid;
        #pragma unroll
        for (int j = 0; j < 4; j++) {
            int cc = j0 + wn * 32 + j * 8 + tc * 2;
            float2 v0, v1;
            if (USE_CORR) {
                __half2 p0 = *(__half2*)&corr[mt][j][0];
                __half2 p1 = *(__half2*)&corr[mt][j][1];
                v0 = make_float2(acc[mt][j][0] + __half2float(p0.x),
                                 acc[mt][j][1] + __half2float(p0.y));
                v1 = make_float2(acc[mt][j][2] + __half2float(p1.x),
                                 acc[mt][j][3] + __half2float(p1.y));
            } else {
                v0 = make_float2(acc[mt][j][0], acc[mt][j][1]);
                v1 = make_float2(acc[mt][j][2], acc[mt][j][3]);
            }
            *(float2*)&Cz[(size_t)r0 * ldc + cc] = v0;
            *(float2*)&Cz[(size_t)(r0 + 8) * ldc + cc] = v1;
        }
    }
}

// ---------------- launch ----------------
extern "C" void kernel_launch(void* const* d_in, const int* in_sizes, int n_in,
                              void* d_out, int out_size)
{
    const float* x = (const float*)d_in[0];   // [n, d]
    const float* w = (const float*)d_in[1];   // [d, d]
    float* out = (float*)d_out;               // [n, d]

    int d = (int)(sqrt((double)in_sizes[1]) + 0.5);
    int n = in_sizes[0] / d;

    float *invs, *Gpart;
    __half *nh, *nTh, *xTh, *WTh, *WTl, *Gh, *Gl, *MTh;
    cudaGetSymbolAddress((void**)&invs, g_invs);
    cudaGetSymbolAddress((void**)&nh, g_norm_h);
    cudaGetSymbolAddress((void**)&nTh, g_normT_h);
    cudaGetSymbolAddress((void**)&xTh, g_xT_h);
    cudaGetSymbolAddress((void**)&WTh, g_WT_h);    cudaGetSymbolAddress((void**)&WTl, g_WT_l);
    cudaGetSymbolAddress((void**)&Gpart, g_Gpart);
    cudaGetSymbolAddress((void**)&Gh, g_G_h);      cudaGetSymbolAddress((void**)&Gl, g_G_l);
    cudaGetSymbolAddress((void**)&MTh, g_MT_h);

    cudaFuncSetAttribute((const void*)k_mma_gemm<1,1>,
                         cudaFuncAttributeMaxDynamicSharedMemorySize, NSTAGE * STAGE_BYTES);
    cudaFuncSetAttribute((const void*)k_mma_gemm<0,0>,
                         cudaFuncAttributeMaxDynamicSharedMemorySize, NSTAGE * STAGE_BYTES);

    dim3 tb(32, 8);

    // idx 0: row norms
    k_rownorm<<<n / 8, 256>>>(x, invs);
    // idx 1: fused prep (nh + xT hi + nT hi)
    k_prep<<<dim3(d / 32, n / 32), tb>>>(x, invs, nh, xTh, nTh);
    // idx 2: W transpose+split (GEMM2 keeps full precision)
    k_tsplit<<<dim3(d / 32, d / 32), tb>>>(w, WTh, WTl, d, d);
    // idx 3: G = nTh @ xTh — single-term, upper-tri grid, ZSPLIT k-split; PROFILED
    k_mma_gemm<0,0><<<dim3(36, 1, ZSPLIT), 512, NSTAGE * STAGE_BYTES>>>(
        nTh, nTh, xTh, xTh, Gpart, n, n / ZSPLIT, d, d * d, 1);
    // idx 4: reduce G partials + mirror lower + split
    k_reduce_split_sym<<<dim3(d / 32, d / 32), tb>>>(Gpart, Gh, Gl);
    // idx 5: M partials = G @ W (full 3-term; K split by ZSPLIT2; reuse Gpart)
    k_mma_gemm<1,1><<<dim3(d / 128, d / 128, ZSPLIT2), 512, NSTAGE * STAGE_BYTES>>>(
        Gh, Gl, WTh, WTl, Gpart, d, d / ZSPLIT2, d, d * d, 0);
    // idx 6: reduce M partials + transpose (hi only)
    k_reduce_tsplit<<<dim3(d / 32, d / 32), tb>>>(Gpart, MTh);
    // idx 7: out = nh @ MTh — single-term
    k_mma_gemm<0,0><<<dim3(d / 128, n / 128, 1), 512, NSTAGE * STAGE_BYTES>>>(
        nh, nh, MTh, MTh, out, d, d, d, 0, 0);
}